// round 2
// baseline (speedup 1.0000x reference)
#include <cuda_runtime.h>

#define IN_CH 512
#define BATCH 8
#define HH 100
#define WW 100
#define NA 9
#define NHEAD 45
#define NHEADP 48

#define CO_TILE 64
#define TY 4
#define TX 32
#define CK 8

// ---- device scratch (allocation-free per harness rules) ----
__device__ float g_feat[BATCH * IN_CH * HH * WW];          // 163.84 MB intermediate
__device__ float g_wt[IN_CH * 9 * IN_CH];                  // conv weights [ci][k][co]
__device__ float g_wh[IN_CH * NHEADP];                     // head weights [ci][co48]

// ---- packed fp32x2 helpers ----
__device__ __forceinline__ unsigned long long pk2(float x, float y) {
    unsigned long long r;
    asm("mov.b64 %0, {%1, %2};" : "=l"(r) : "r"(__float_as_int(x)), "r"(__float_as_int(y)));
    return r;
}
__device__ __forceinline__ void upk2(unsigned long long v, float& x, float& y) {
    int a, b;
    asm("mov.b64 {%0, %1}, %2;" : "=r"(a), "=r"(b) : "l"(v));
    x = __int_as_float(a); y = __int_as_float(b);
}
__device__ __forceinline__ void fma2(unsigned long long& d, unsigned long long a, unsigned long long b) {
    asm("fma.rn.f32x2 %0, %1, %2, %0;" : "+l"(d) : "l"(a), "l"(b));
}

// ---- weight transforms (run once per launch; tiny) ----
__global__ void transform_wrpn(const float* __restrict__ w) {
    int idx = blockIdx.x * blockDim.x + threadIdx.x;
    if (idx >= IN_CH * 9 * IN_CH) return;
    int co = idx % IN_CH;
    int k  = (idx / IN_CH) % 9;
    int ci = idx / (IN_CH * 9);
    g_wt[idx] = w[(co * IN_CH + ci) * 9 + k];
}

__global__ void transform_whead(const float* __restrict__ wcls, const float* __restrict__ wbbox) {
    int idx = blockIdx.x * blockDim.x + threadIdx.x;
    if (idx >= IN_CH * NHEADP) return;
    int co = idx % NHEADP;
    int ci = idx / NHEADP;
    float v = 0.0f;
    if (co < NA)          v = wcls[co * IN_CH + ci];
    else if (co < NHEAD)  v = wbbox[(co - NA) * IN_CH + ci];
    g_wh[idx] = v;
}

// ---- main 3x3 conv + ReLU (implicit GEMM, fp32x2 packed FMA) ----
// grid: x = co groups (8), y = x-tiles (4), z = batch*ytiles (8*25)
__global__ __launch_bounds__(256)
void conv3x3_relu(const float* __restrict__ x, const float* __restrict__ brpn) {
    __shared__ float sIn[CK][TY + 2][36];          // padded rows; 16B aligned slices
    __shared__ float sW[CK][9][CO_TILE];

    const int tid  = threadIdx.x;
    const int cg   = tid >> 5;                     // co subgroup 0..7 (one per warp)
    const int pg   = tid & 31;
    const int prow = pg >> 3;                      // 0..3
    const int xq   = (pg & 7) << 2;                // 0,4,...,28

    const int co0 = blockIdx.x * CO_TILE;
    const int tx0 = blockIdx.y * TX;
    const int bz  = blockIdx.z;
    const int b   = bz / 25;
    const int gy0 = (bz % 25) * TY;

    unsigned long long acc[4][4];                  // [co-pair][pos] packed fp32x2
    #pragma unroll
    for (int p = 0; p < 4; p++)
        #pragma unroll
        for (int i = 0; i < 4; i++) acc[p][i] = 0ull;

    const float* xb = x + (size_t)b * IN_CH * HH * WW;

    for (int ci0 = 0; ci0 < IN_CH; ci0 += CK) {
        // stage input patch (CK ci) x 6 rows x 34 cols, zero-padded at borders
        for (int e = tid; e < CK * 6 * 34; e += 256) {
            int c  = e % 34;
            int r  = (e / 34) % 6;
            int ci = e / (34 * 6);
            int gx = tx0 - 1 + c;
            int gy = gy0 - 1 + r;
            float v = 0.0f;
            if (gx >= 0 && gx < WW && gy >= 0 && gy < HH)
                v = xb[(size_t)(ci0 + ci) * HH * WW + gy * WW + gx];
            sIn[ci][r][c] = v;
        }
        // stage weights (coalesced thanks to [ci][k][co] layout)
        for (int e = tid; e < CK * 9 * CO_TILE; e += 256) {
            int co = e % CO_TILE;
            int k  = (e / CO_TILE) % 9;
            int ci = e / (CO_TILE * 9);
            sW[ci][k][co] = g_wt[((size_t)(ci0 + ci) * 9 + k) * IN_CH + co0 + co];
        }
        __syncthreads();

        for (int ci = 0; ci < CK; ci++) {
            #pragma unroll
            for (int ky = 0; ky < 3; ky++) {
                const float* rowp = &sIn[ci][prow + ky][xq];
                float4 fa = *(const float4*)rowp;          // f0..f3 (16B aligned)
                float2 fb = *(const float2*)(rowp + 4);    // f4,f5  (8B aligned)
                float f[6];
                f[0] = fa.x; f[1] = fa.y; f[2] = fa.z; f[3] = fa.w;
                f[4] = fb.x; f[5] = fb.y;
                #pragma unroll
                for (int kx = 0; kx < 3; kx++) {
                    const float4* wp = (const float4*)&sW[ci][ky * 3 + kx][cg * 8];
                    float4 w0 = wp[0];
                    float4 w1 = wp[1];
                    unsigned long long wpair[4];
                    wpair[0] = pk2(w0.x, w0.y);
                    wpair[1] = pk2(w0.z, w0.w);
                    wpair[2] = pk2(w1.x, w1.y);
                    wpair[3] = pk2(w1.z, w1.w);
                    #pragma unroll
                    for (int i = 0; i < 4; i++) {
                        unsigned long long din = pk2(f[kx + i], f[kx + i]);
                        #pragma unroll
                        for (int p = 0; p < 4; p++)
                            fma2(acc[p][i], din, wpair[p]);
                    }
                }
            }
        }
        __syncthreads();
    }

    // epilogue: bias + relu + store feat
    const int gy = gy0 + prow;
    #pragma unroll
    for (int p = 0; p < 4; p++) {
        int coA = co0 + cg * 8 + p * 2;
        int coB = coA + 1;
        float bA = brpn[coA];
        float bB = brpn[coB];
        #pragma unroll
        for (int i = 0; i < 4; i++) {
            int gx = tx0 + xq + i;
            if (gx >= WW) continue;
            float lo, hi;
            upk2(acc[p][i], lo, hi);
            g_feat[((size_t)(b * IN_CH + coA) * HH + gy) * WW + gx] = fmaxf(lo + bA, 0.0f);
            g_feat[((size_t)(b * IN_CH + coB) * HH + gy) * WW + gx] = fmaxf(hi + bB, 0.0f);
        }
    }
}

// ---- fused 1x1 heads: cls (9) + bbox (36) ----
__global__ __launch_bounds__(256)
void heads_kernel(const float* __restrict__ bcls, const float* __restrict__ bbbox,
                  float* __restrict__ out) {
    __shared__ float sw[128][NHEADP];
    const int idx    = blockIdx.x * 256 + threadIdx.x;    // flat position id
    const bool active = idx < BATCH * HH * WW;
    const int b  = idx / (HH * WW);
    const int hw = idx % (HH * WW);
    const float* fp = g_feat + (size_t)b * IN_CH * HH * WW + hw;

    float acc[NHEADP];
    #pragma unroll
    for (int c = 0; c < NHEADP; c++) acc[c] = 0.0f;

    for (int ci0 = 0; ci0 < IN_CH; ci0 += 128) {
        __syncthreads();
        for (int e = threadIdx.x; e < 128 * NHEADP; e += 256)
            ((float*)sw)[e] = g_wh[(size_t)ci0 * NHEADP + e];
        __syncthreads();
        if (active) {
            for (int ci = 0; ci < 128; ci++) {
                float v = fp[(size_t)(ci0 + ci) * HH * WW];
                const float4* wr = (const float4*)sw[ci];
                #pragma unroll
                for (int q = 0; q < NHEADP / 4; q++) {
                    float4 w = wr[q];
                    acc[q * 4 + 0] += v * w.x;
                    acc[q * 4 + 1] += v * w.y;
                    acc[q * 4 + 2] += v * w.z;
                    acc[q * 4 + 3] += v * w.w;
                }
            }
        }
    }

    if (active) {
        // out = [cls (8*9*100*100)] ++ [bbox (8*36*100*100)]
        #pragma unroll
        for (int co = 0; co < NA; co++)
            out[((size_t)(b * NA + co)) * (HH * WW) + hw] = acc[co] + bcls[co];
        float* outb = out + (size_t)BATCH * NA * HH * WW;
        #pragma unroll
        for (int j = 0; j < 36; j++)
            outb[((size_t)(b * 36 + j)) * (HH * WW) + hw] = acc[NA + j] + bbbox[j];
    }
}

extern "C" void kernel_launch(void* const* d_in, const int* in_sizes, int n_in,
                              void* d_out, int out_size) {
    const float* x      = (const float*)d_in[0];
    const float* w_rpn  = (const float*)d_in[1];
    const float* b_rpn  = (const float*)d_in[2];
    const float* w_cls  = (const float*)d_in[3];
    const float* b_cls  = (const float*)d_in[4];
    const float* w_bbox = (const float*)d_in[5];
    const float* b_bbox = (const float*)d_in[6];
    float* out = (float*)d_out;

    transform_wrpn<<<(IN_CH * 9 * IN_CH + 255) / 256, 256>>>(w_rpn);
    transform_whead<<<(IN_CH * NHEADP + 255) / 256, 256>>>(w_cls, w_bbox);

    dim3 g1(IN_CH / CO_TILE, (WW + TX - 1) / TX, BATCH * (HH / TY));
    conv3x3_relu<<<g1, 256>>>(x, b_rpn);

    heads_kernel<<<(BATCH * HH * WW + 255) / 256, 256>>>(b_cls, b_bbox, out);
}

// round 6
// speedup vs baseline: 3.6568x; 3.6568x over previous
#include <cuda_runtime.h>
#include <cuda_bf16.h>
#include <cstdint>

#define IN_CH 512
#define BATCH 8
#define HH 100
#define WW 100
#define NA 9
#define NHEAD 45
#define NHEADP 48

#define PW 102                       // padded grid width/height
#define NPOS (PW * PW)               // 10404 padded positions per batch
#define BM 128                       // co per CTA
#define BN 128                       // positions per CTA
#define BK 64                        // ci per chunk
#define NT_PER_B 82                  // ceil(10404/128)
#define NCHUNK 72                    // 9 kernel offsets * 8 ci-chunks
#define XROWS (BATCH * NPOS + 768)   // slack for shifted tail-tile reads

// stage layout (bytes within one pipeline stage): 4 x 16KB tiles
#define OFF_WHI 0
#define OFF_WLO 16384
#define OFF_XHI 32768
#define OFF_XLO 49152
#define STAGE_BYTES 65536
#define NSTAGE 3
#define DSMEM_BYTES (NSTAGE * STAGE_BYTES)

// ---------------- device scratch (allocation-free) ----------------
__device__ float g_feat[BATCH * IN_CH * HH * WW];           // fp32 feature map
__device__ __nv_bfloat16 g_xhi[(size_t)XROWS * IN_CH];      // padded channels-last x, hi
__device__ __nv_bfloat16 g_xlo[(size_t)XROWS * IN_CH];      // lo
__device__ __nv_bfloat16 g_whi[9 * IN_CH * IN_CH];          // weights [k9][co][ci], hi
__device__ __nv_bfloat16 g_wlo[9 * IN_CH * IN_CH];          // lo
__device__ float g_wh[IN_CH * NHEADP];                      // head weights [ci][co48]

// ---------------- PTX helpers (all base sm_80-era features) ----------------
__device__ __forceinline__ uint32_t smem_u32(const void* p) {
    uint32_t a;
    asm("{ .reg .u64 t; cvta.to.shared.u64 t, %1; cvt.u32.u64 %0, t; }" : "=r"(a) : "l"(p));
    return a;
}
__device__ __forceinline__ void cp16(uint32_t sdst, const void* gsrc) {
    asm volatile("cp.async.cg.shared.global [%0], [%1], 16;" :: "r"(sdst), "l"(gsrc) : "memory");
}
#define CP_COMMIT() asm volatile("cp.async.commit_group;" ::: "memory")
#define CP_WAIT(n)  asm volatile("cp.async.wait_group %0;" :: "n"(n) : "memory")

__device__ __forceinline__ void ldsm4(uint32_t* r, uint32_t addr) {
    asm volatile("ldmatrix.sync.aligned.m8n8.x4.shared.b16 {%0,%1,%2,%3}, [%4];"
        : "=r"(r[0]), "=r"(r[1]), "=r"(r[2]), "=r"(r[3]) : "r"(addr));
}
__device__ __forceinline__ void mma16816(float* d, const uint32_t* a, const uint32_t* b) {
    asm volatile(
        "mma.sync.aligned.m16n8k16.row.col.f32.bf16.bf16.f32 "
        "{%0,%1,%2,%3}, {%4,%5,%6,%7}, {%8,%9}, {%0,%1,%2,%3};"
        : "+f"(d[0]), "+f"(d[1]), "+f"(d[2]), "+f"(d[3])
        : "r"(a[0]), "r"(a[1]), "r"(a[2]), "r"(a[3]), "r"(b[0]), "r"(b[1]));
}
__device__ __forceinline__ uint32_t swz(uint32_t off) { return off ^ ((off >> 3) & 0x70); }

// ---------------- transform kernels ----------------
__global__ void wsplit_kernel(const float* __restrict__ w) {
    int idx = blockIdx.x * blockDim.x + threadIdx.x;
    if (idx >= 9 * IN_CH * IN_CH) return;
    int k9 = idx / (IN_CH * IN_CH);
    int rem = idx % (IN_CH * IN_CH);
    int co = rem / IN_CH, ci = rem % IN_CH;
    float v = w[((size_t)co * IN_CH + ci) * 9 + k9];
    __nv_bfloat16 hi = __float2bfloat16(v);
    __nv_bfloat16 lo = __float2bfloat16(v - __bfloat162float(hi));
    g_whi[idx] = hi;                                        // [k9][co][ci]
    g_wlo[idx] = lo;
}

// x -> padded channels-last bf16 hi/lo via smem transpose
__global__ void xsplit_kernel(const float* __restrict__ x) {
    __shared__ float tile[32][33];
    int xc = blockIdx.x, y = blockIdx.y, b = blockIdx.z;
    int x0 = xc * 32;
    for (int cc0 = 0; cc0 < IN_CH; cc0 += 32) {
        #pragma unroll
        for (int it = 0; it < 4; it++) {
            int ci = cc0 + threadIdx.y + it * 8;
            int xx = x0 + threadIdx.x;
            float v = 0.0f;
            if (xx < WW) v = x[(((size_t)b * IN_CH + ci) * HH + y) * WW + xx];
            tile[threadIdx.y + it * 8][threadIdx.x] = v;
        }
        __syncthreads();
        #pragma unroll
        for (int j = 0; j < 4; j++) {
            int xl = threadIdx.y * 4 + j;
            int xx = x0 + xl;
            if (xx < WW) {
                float v = tile[threadIdx.x][xl];
                __nv_bfloat16 hi = __float2bfloat16(v);
                __nv_bfloat16 lo = __float2bfloat16(v - __bfloat162float(hi));
                size_t row = (size_t)b * NPOS + (size_t)(y + 1) * PW + (xx + 1);
                g_xhi[row * IN_CH + cc0 + threadIdx.x] = hi;
                g_xlo[row * IN_CH + cc0 + threadIdx.x] = lo;
            }
        }
        __syncthreads();
    }
}

// zero the padded border rows/cols (404 positions per batch)
__global__ void xborder_kernel() {
    int idx = blockIdx.x * blockDim.x + threadIdx.x;
    if (idx >= BATCH * 404 * IN_CH) return;
    int b = idx / (404 * IN_CH);
    int r = idx % (404 * IN_CH);
    int bp = r / IN_CH, ci = r % IN_CH;
    int p;
    if (bp < 102)       p = bp;
    else if (bp < 204)  p = 101 * PW + (bp - 102);
    else { int q = bp - 204; p = (1 + q / 2) * PW + ((q & 1) ? 101 : 0); }
    size_t e = ((size_t)b * NPOS + p) * IN_CH + ci;
    g_xhi[e] = __float2bfloat16(0.0f);
    g_xlo[e] = __float2bfloat16(0.0f);
}

__global__ void transform_whead(const float* __restrict__ wcls, const float* __restrict__ wbbox) {
    int idx = blockIdx.x * blockDim.x + threadIdx.x;
    if (idx >= IN_CH * NHEADP) return;
    int co = idx % NHEADP, ci = idx / NHEADP;
    float v = 0.0f;
    if (co < NA)         v = wcls[co * IN_CH + ci];
    else if (co < NHEAD) v = wbbox[(co - NA) * IN_CH + ci];
    g_wh[idx] = v;
}

// ---------------- main conv: mma.sync implicit GEMM, bf16 hi/lo 3-pass ----------------
extern __shared__ char dsm_raw[];

__global__ __launch_bounds__(256, 1)
void conv_mma(const float* __restrict__ brpn) {
    const uint32_t base = smem_u32(dsm_raw);
    const int tid  = threadIdx.x;
    const int lane = tid & 31;
    const int wid  = tid >> 5;
    const int wm   = wid & 1;          // warp co-tile   (2)
    const int wn   = wid >> 1;         // warp pos-tile  (4)
    const int co0  = blockIdx.x * BM;
    const int p0   = blockIdx.y * BN;
    const int bz   = blockIdx.z;
    const size_t bbase = (size_t)bz * NPOS;

    float acc[4][4][4];
    #pragma unroll
    for (int mt = 0; mt < 4; mt++)
        #pragma unroll
        for (int nt = 0; nt < 4; nt++)
            #pragma unroll
            for (int i = 0; i < 4; i++) acc[mt][nt][i] = 0.0f;

    // ldmatrix lane-derived constants
    const int arowoff = lane & 15;
    const int ahalf   = lane >> 4;                       // k 8-chunk for A mats
    const int browoff = (lane & 7) + ((lane >> 4) << 3);
    const int bhalf   = (lane >> 3) & 1;                 // k 8-chunk for B mats
    const int l7      = lane & 7;

    uint32_t aoff[4], boff[2];
    #pragma unroll
    for (int mt = 0; mt < 4; mt++) aoff[mt] = (uint32_t)(wm * 64 + mt * 16 + arowoff) * 128u;
    #pragma unroll
    for (int np = 0; np < 2; np++) boff[np] = (uint32_t)(wn * 32 + np * 16 + browoff) * 128u;

    // ---- staging: one chunk = 64KB (Whi/Wlo 128x64, Xhi/Xlo 128x64), SW128 swizzled
    auto stage_chunk = [&](int c, uint32_t sb) {
        int k9 = c >> 3, kc = c & 7;
        int shift = (k9 / 3) * PW + (k9 % 3);
        size_t wrow = ((size_t)k9 * IN_CH + co0);
        #pragma unroll
        for (int i = 0; i < 4; i++) {
            int e = i * 256 + tid;                       // 0..1023
            int rr = e >> 3, cc = e & 7;
            uint32_t so = swz((uint32_t)(rr * 128 + cc * 16));
            size_t go = (wrow + rr) * IN_CH + (size_t)kc * 64 + cc * 8;
            cp16(sb + OFF_WHI + so, g_whi + go);
            cp16(sb + OFF_WLO + so, g_wlo + go);
        }
        size_t xrow = bbase + (size_t)(p0 + shift);
        #pragma unroll
        for (int i = 0; i < 4; i++) {
            int e = i * 256 + tid;
            int rr = e >> 3, cc = e & 7;
            uint32_t so = swz((uint32_t)(rr * 128 + cc * 16));
            size_t go = (xrow + rr) * IN_CH + (size_t)kc * 64 + cc * 8;
            cp16(sb + OFF_XHI + so, g_xhi + go);
            cp16(sb + OFF_XLO + so, g_xlo + go);
        }
        CP_COMMIT();
    };

    stage_chunk(0, base);
    stage_chunk(1, base + STAGE_BYTES);

    for (int c = 0; c < NCHUNK; c++) {
        if (c + 2 < NCHUNK) { CP_WAIT(1); } else { CP_WAIT(0); }
        __syncthreads();
        if (c + 2 < NCHUNK)
            stage_chunk(c + 2, base + (uint32_t)((c + 2) % NSTAGE) * STAGE_BYTES);

        const uint32_t sb = base + (uint32_t)(c % NSTAGE) * STAGE_BYTES;
        #pragma unroll
        for (int ks = 0; ks < 4; ks++) {
            const uint32_t acol = (uint32_t)((2 * ks + ahalf) ^ l7) << 4;
            const uint32_t bcol = (uint32_t)((2 * ks + bhalf) ^ l7) << 4;
            uint32_t ah[4][4], al[4][4], bh[2][4], bl[2][4];
            #pragma unroll
            for (int mt = 0; mt < 4; mt++) {
                ldsm4(ah[mt], sb + OFF_WHI + aoff[mt] + acol);
                ldsm4(al[mt], sb + OFF_WLO + aoff[mt] + acol);
            }
            #pragma unroll
            for (int np = 0; np < 2; np++) {
                ldsm4(bh[np], sb + OFF_XHI + boff[np] + bcol);
                ldsm4(bl[np], sb + OFF_XLO + boff[np] + bcol);
            }
            #pragma unroll
            for (int mt = 0; mt < 4; mt++)
                #pragma unroll
                for (int nt = 0; nt < 4; nt++) {
                    const uint32_t* bhp = &bh[nt >> 1][(nt & 1) * 2];
                    const uint32_t* blp = &bl[nt >> 1][(nt & 1) * 2];
                    mma16816(acc[mt][nt], ah[mt], bhp);   // hi*hi
                    mma16816(acc[mt][nt], ah[mt], blp);   // hi*lo
                    mma16816(acc[mt][nt], al[mt], bhp);   // lo*hi
                }
        }
    }

    // ---- epilogue: bias + relu, padded-pos -> (y,x) with bounds check
    #pragma unroll
    for (int mt = 0; mt < 4; mt++) {
        const int r0 = co0 + wm * 64 + mt * 16 + (lane >> 2);
        const float bv0 = brpn[r0];
        const float bv1 = brpn[r0 + 8];
        const size_t fb0 = ((size_t)(bz * IN_CH) + r0) * (HH * WW);
        const size_t fb1 = ((size_t)(bz * IN_CH) + r0 + 8) * (HH * WW);
        #pragma unroll
        for (int nt = 0; nt < 4; nt++) {
            const int p = p0 + wn * 32 + nt * 8 + ((lane & 3) << 1);
            #pragma unroll
            for (int j = 0; j < 2; j++) {
                const int pp = p + j;
                const int yy = pp / PW;
                const int xx = pp - yy * PW;
                if (yy < HH && xx < WW) {
                    const size_t o = (size_t)yy * WW + xx;
                    g_feat[fb0 + o] = fmaxf(acc[mt][nt][0 + j] + bv0, 0.0f);
                    g_feat[fb1 + o] = fmaxf(acc[mt][nt][2 + j] + bv1, 0.0f);
                }
            }
        }
    }
}

// ---------------- 1x1 heads (unchanged from passing R2 kernel) ----------------
__global__ __launch_bounds__(256)
void heads_kernel(const float* __restrict__ bcls, const float* __restrict__ bbbox,
                  float* __restrict__ out) {
    __shared__ float sw[128][NHEADP];
    const int idx = blockIdx.x * 256 + threadIdx.x;
    const bool active = idx < BATCH * HH * WW;
    const int b = idx / (HH * WW);
    const int hw = idx % (HH * WW);
    const float* fp = g_feat + (size_t)b * IN_CH * HH * WW + hw;

    float acc[NHEADP];
    #pragma unroll
    for (int c = 0; c < NHEADP; c++) acc[c] = 0.0f;

    for (int ci0 = 0; ci0 < IN_CH; ci0 += 128) {
        __syncthreads();
        for (int e = threadIdx.x; e < 128 * NHEADP; e += 256)
            ((float*)sw)[e] = g_wh[(size_t)ci0 * NHEADP + e];
        __syncthreads();
        if (active) {
            for (int ci = 0; ci < 128; ci++) {
                float v = fp[(size_t)(ci0 + ci) * HH * WW];
                const float4* wr = (const float4*)sw[ci];
                #pragma unroll
                for (int q = 0; q < NHEADP / 4; q++) {
                    float4 w = wr[q];
                    acc[q * 4 + 0] += v * w.x;
                    acc[q * 4 + 1] += v * w.y;
                    acc[q * 4 + 2] += v * w.z;
                    acc[q * 4 + 3] += v * w.w;
                }
            }
        }
    }

    if (active) {
        #pragma unroll
        for (int co = 0; co < NA; co++)
            out[((size_t)(b * NA + co)) * (HH * WW) + hw] = acc[co] + bcls[co];
        float* outb = out + (size_t)BATCH * NA * HH * WW;
        #pragma unroll
        for (int j = 0; j < 36; j++)
            outb[((size_t)(b * 36 + j)) * (HH * WW) + hw] = acc[NA + j] + bbbox[j];
    }
}

// ---------------- launch ----------------
extern "C" void kernel_launch(void* const* d_in, const int* in_sizes, int n_in,
                              void* d_out, int out_size) {
    const float* x      = (const float*)d_in[0];
    const float* w_rpn  = (const float*)d_in[1];
    const float* b_rpn  = (const float*)d_in[2];
    const float* w_cls  = (const float*)d_in[3];
    const float* b_cls  = (const float*)d_in[4];
    const float* w_bbox = (const float*)d_in[5];
    const float* b_bbox = (const float*)d_in[6];
    float* out = (float*)d_out;

    cudaFuncSetAttribute(conv_mma, cudaFuncAttributeMaxDynamicSharedMemorySize, DSMEM_BYTES);

    wsplit_kernel<<<(9 * IN_CH * IN_CH + 255) / 256, 256>>>(w_rpn);
    transform_whead<<<(IN_CH * NHEADP + 255) / 256, 256>>>(w_cls, w_bbox);
    xborder_kernel<<<(BATCH * 404 * IN_CH + 255) / 256, 256>>>();
    xsplit_kernel<<<dim3(4, HH, BATCH), dim3(32, 8)>>>(x);

    conv_mma<<<dim3(IN_CH / BM, NT_PER_B, BATCH), 256, DSMEM_BYTES>>>(b_rpn);

    heads_kernel<<<(BATCH * HH * WW + 255) / 256, 256>>>(b_cls, b_bbox, out);
}

// round 7
// speedup vs baseline: 3.8529x; 1.0536x over previous
#include <cuda_runtime.h>
#include <cuda_bf16.h>
#include <cstdint>

#define IN_CH 512
#define BATCH 8
#define HH 100
#define WW 100
#define NA 9
#define NHEAD 45
#define NHEADP 48

#define PW 102                       // padded grid width/height
#define NPOS (PW * PW)               // 10404 padded positions per batch
#define BM 128                       // co per CTA
#define BN 192                       // positions per CTA
#define NT_PER_B 55                  // ceil(10404/192)
#define NITER 72                     // 24 (ky,kc) groups * 3 kx
#define NGRP 24                      // 3 ky * 8 ci-chunks
#define XWIN 194                     // BN + 2 rows staged per x window
#define XROWS (BATCH * NPOS + 768)   // slack for shifted tail-tile reads

// smem layout: 3 w buffers + 2 x buffers
#define WBUF_BYTES 32768             // whi 16K + wlo 16K (128 co x 64 ci)
#define XBUF_BYTES 49664             // xhi 24832 + xlo 24832 (194 rows x 128B)
#define OFF_X0 (3 * WBUF_BYTES)      // 98304
#define DSMEM_BYTES (3 * WBUF_BYTES + 2 * XBUF_BYTES)   // 197632 (193KB)

// ---------------- device scratch (allocation-free) ----------------
__device__ float g_feat[BATCH * IN_CH * HH * WW];           // fp32 feature map
__device__ __nv_bfloat16 g_xhi[(size_t)XROWS * IN_CH];      // padded channels-last x, hi
__device__ __nv_bfloat16 g_xlo[(size_t)XROWS * IN_CH];      // lo
__device__ __nv_bfloat16 g_whi[9 * IN_CH * IN_CH];          // weights [k9][co][ci], hi
__device__ __nv_bfloat16 g_wlo[9 * IN_CH * IN_CH];          // lo
__device__ float g_wh[IN_CH * NHEADP];                      // head weights [ci][co48]

// ---------------- PTX helpers (base sm_80-era features only) ----------------
__device__ __forceinline__ uint32_t smem_u32(const void* p) {
    uint32_t a;
    asm("{ .reg .u64 t; cvta.to.shared.u64 t, %1; cvt.u32.u64 %0, t; }" : "=r"(a) : "l"(p));
    return a;
}
__device__ __forceinline__ void cp16(uint32_t sdst, const void* gsrc) {
    asm volatile("cp.async.cg.shared.global [%0], [%1], 16;" :: "r"(sdst), "l"(gsrc) : "memory");
}
#define CP_COMMIT() asm volatile("cp.async.commit_group;" ::: "memory")
#define CP_WAIT(n)  asm volatile("cp.async.wait_group %0;" :: "n"(n) : "memory")

__device__ __forceinline__ void ldsm4(uint32_t* r, uint32_t addr) {
    asm volatile("ldmatrix.sync.aligned.m8n8.x4.shared.b16 {%0,%1,%2,%3}, [%4];"
        : "=r"(r[0]), "=r"(r[1]), "=r"(r[2]), "=r"(r[3]) : "r"(addr));
}
__device__ __forceinline__ void mma16816(float* d, const uint32_t* a, const uint32_t* b) {
    asm volatile(
        "mma.sync.aligned.m16n8k16.row.col.f32.bf16.bf16.f32 "
        "{%0,%1,%2,%3}, {%4,%5,%6,%7}, {%8,%9}, {%0,%1,%2,%3};"
        : "+f"(d[0]), "+f"(d[1]), "+f"(d[2]), "+f"(d[3])
        : "r"(a[0]), "r"(a[1]), "r"(a[2]), "r"(a[3]), "r"(b[0]), "r"(b[1]));
}
__device__ __forceinline__ uint32_t swz(uint32_t off) { return off ^ ((off >> 3) & 0x70); }

// ---------------- transform kernels (unchanged from passing R6) ----------------
__global__ void wsplit_kernel(const float* __restrict__ w) {
    int idx = blockIdx.x * blockDim.x + threadIdx.x;
    if (idx >= 9 * IN_CH * IN_CH) return;
    int k9 = idx / (IN_CH * IN_CH);
    int rem = idx % (IN_CH * IN_CH);
    int co = rem / IN_CH, ci = rem % IN_CH;
    float v = w[((size_t)co * IN_CH + ci) * 9 + k9];
    __nv_bfloat16 hi = __float2bfloat16(v);
    __nv_bfloat16 lo = __float2bfloat16(v - __bfloat162float(hi));
    g_whi[idx] = hi;                                        // [k9][co][ci]
    g_wlo[idx] = lo;
}

__global__ void xsplit_kernel(const float* __restrict__ x) {
    __shared__ float tile[32][33];
    int xc = blockIdx.x, y = blockIdx.y, b = blockIdx.z;
    int x0 = xc * 32;
    for (int cc0 = 0; cc0 < IN_CH; cc0 += 32) {
        #pragma unroll
        for (int it = 0; it < 4; it++) {
            int ci = cc0 + threadIdx.y + it * 8;
            int xx = x0 + threadIdx.x;
            float v = 0.0f;
            if (xx < WW) v = x[(((size_t)b * IN_CH + ci) * HH + y) * WW + xx];
            tile[threadIdx.y + it * 8][threadIdx.x] = v;
        }
        __syncthreads();
        #pragma unroll
        for (int j = 0; j < 4; j++) {
            int xl = threadIdx.y * 4 + j;
            int xx = x0 + xl;
            if (xx < WW) {
                float v = tile[threadIdx.x][xl];
                __nv_bfloat16 hi = __float2bfloat16(v);
                __nv_bfloat16 lo = __float2bfloat16(v - __bfloat162float(hi));
                size_t row = (size_t)b * NPOS + (size_t)(y + 1) * PW + (xx + 1);
                g_xhi[row * IN_CH + cc0 + threadIdx.x] = hi;
                g_xlo[row * IN_CH + cc0 + threadIdx.x] = lo;
            }
        }
        __syncthreads();
    }
}

__global__ void xborder_kernel() {
    int idx = blockIdx.x * blockDim.x + threadIdx.x;
    if (idx >= BATCH * 404 * IN_CH) return;
    int b = idx / (404 * IN_CH);
    int r = idx % (404 * IN_CH);
    int bp = r / IN_CH, ci = r % IN_CH;
    int p;
    if (bp < 102)       p = bp;
    else if (bp < 204)  p = 101 * PW + (bp - 102);
    else { int q = bp - 204; p = (1 + q / 2) * PW + ((q & 1) ? 101 : 0); }
    size_t e = ((size_t)b * NPOS + p) * IN_CH + ci;
    g_xhi[e] = __float2bfloat16(0.0f);
    g_xlo[e] = __float2bfloat16(0.0f);
}

__global__ void transform_whead(const float* __restrict__ wcls, const float* __restrict__ wbbox) {
    int idx = blockIdx.x * blockDim.x + threadIdx.x;
    if (idx >= IN_CH * NHEADP) return;
    int co = idx % NHEADP, ci = idx / NHEADP;
    float v = 0.0f;
    if (co < NA)         v = wcls[co * IN_CH + ci];
    else if (co < NHEAD) v = wbbox[(co - NA) * IN_CH + ci];
    g_wh[idx] = v;
}

// ---------------- main conv: mma.sync implicit GEMM, x-reuse across kx ----------------
extern __shared__ char dsm_raw[];

__global__ __launch_bounds__(256, 1)
void conv_mma(const float* __restrict__ brpn) {
    const uint32_t base = smem_u32(dsm_raw);
    const uint32_t xbase = base + OFF_X0;
    const int tid  = threadIdx.x;
    const int lane = tid & 31;
    const int wid  = tid >> 5;
    const int wm   = wid & 1;          // warp co-tile   (2 x 64)
    const int wn   = wid >> 1;         // warp pos-tile  (4 x 48)
    const int co0  = blockIdx.x * BM;
    const int p0   = blockIdx.y * BN;
    const int bz   = blockIdx.z;
    const size_t bbase = (size_t)bz * NPOS;

    float acc[4][6][4];
    #pragma unroll
    for (int mt = 0; mt < 4; mt++)
        #pragma unroll
        for (int nt = 0; nt < 6; nt++)
            #pragma unroll
            for (int i = 0; i < 4; i++) acc[mt][nt][i] = 0.0f;

    // ldmatrix lane-derived constants (identical mapping to verified R6 kernel)
    const int arowoff = lane & 15;
    const int ahalf   = lane >> 4;
    const int browoff = (lane & 7) + ((lane >> 4) << 3);
    const int bhalf   = (lane >> 3) & 1;
    const int l7      = lane & 7;

    uint32_t aoff[4];
    #pragma unroll
    for (int mt = 0; mt < 4; mt++) aoff[mt] = (uint32_t)(wm * 64 + mt * 16 + arowoff) * 128u;

    // ---- staging helpers ----
    // w tile: 128 co x 64 ci (hi+lo), SW128 swizzled
    auto stage_w = [&](int k9, int kc, uint32_t sb) {
        size_t wrow = (size_t)k9 * IN_CH + co0;
        #pragma unroll
        for (int i = 0; i < 4; i++) {
            int e = i * 256 + tid;                       // 0..1023
            int rr = e >> 3, cc = e & 7;
            uint32_t so = swz((uint32_t)(rr * 128 + cc * 16));
            size_t go = (wrow + rr) * IN_CH + (size_t)kc * 64 + cc * 8;
            cp16(sb + so, g_whi + go);
            cp16(sb + 16384 + so, g_wlo + go);
        }
    };
    // x window: 194 rows x 64 ci (hi+lo), covers kx in {0,1,2}
    auto stage_x = [&](int ky, int kc, uint32_t sb) {
        size_t xrow = bbase + (size_t)(p0 + ky * PW);
        for (int e = tid; e < XWIN * 8; e += 256) {
            int rr = e >> 3, cc = e & 7;
            uint32_t so = swz((uint32_t)(rr * 128 + cc * 16));
            size_t go = (xrow + rr) * IN_CH + (size_t)kc * 64 + cc * 8;
            cp16(sb + so, g_xhi + go);
            cp16(sb + 24832 + so, g_xlo + go);
        }
    };

    // ---- prologue: G0 = {X(0), W(0)}, G1 = {W(1)} ----
    stage_x(0, 0, xbase);
    stage_w(0, 0, base);
    CP_COMMIT();
    stage_w(1, 0, base + WBUF_BYTES);
    CP_COMMIT();

    // ---- main loop: iter i -> group g=i/3 (ky=g/8, kc=g%8), offset kx=i%3 ----
    for (int i = 0; i < NITER; i++) {
        const int g  = i / 3;
        const int kx = i - 3 * g;
        CP_WAIT(1);                 // exactly: all groups up to G(i) complete
        __syncthreads();

        // prefetch G(i+2): X(g+1) folded in at kx==1, W(i+2); always commit
        {
            if (kx == 1) {
                int gn = g + 1;
                if (gn < NGRP)
                    stage_x(gn >> 3, gn & 7, xbase + (uint32_t)(gn & 1) * XBUF_BYTES);
            }
            int i2 = i + 2;
            if (i2 < NITER) {
                int g2 = i2 / 3;
                stage_w((g2 >> 3) * 3 + (i2 - 3 * g2), g2 & 7,
                        base + (uint32_t)(i2 % 3) * WBUF_BYTES);
            }
            CP_COMMIT();
        }

        const uint32_t wb = base + (uint32_t)(i % 3) * WBUF_BYTES;
        const uint32_t xb = xbase + (uint32_t)(g & 1) * XBUF_BYTES;
        const int l7x = (l7 + kx) & 7;
        const uint32_t brow = (uint32_t)(wn * 48 + browoff + kx) * 128u;

        #pragma unroll
        for (int ks = 0; ks < 4; ks++) {
            const uint32_t acol = (uint32_t)((2 * ks + ahalf) ^ l7) << 4;
            const uint32_t bcol = (uint32_t)((2 * ks + bhalf) ^ l7x) << 4;
            uint32_t ah[4][4], al[4][4], bh[3][4], bl[3][4];
            #pragma unroll
            for (int mt = 0; mt < 4; mt++) {
                ldsm4(ah[mt], wb + aoff[mt] + acol);
                ldsm4(al[mt], wb + 16384 + aoff[mt] + acol);
            }
            #pragma unroll
            for (int np = 0; np < 3; np++) {
                uint32_t ba = xb + brow + (uint32_t)(np * 16) * 128u + bcol;
                ldsm4(bh[np], ba);
                ldsm4(bl[np], ba + 24832);
            }
            #pragma unroll
            for (int mt = 0; mt < 4; mt++)
                #pragma unroll
                for (int nt = 0; nt < 6; nt++) {
                    const uint32_t* bhp = &bh[nt >> 1][(nt & 1) * 2];
                    const uint32_t* blp = &bl[nt >> 1][(nt & 1) * 2];
                    mma16816(acc[mt][nt], ah[mt], bhp);   // hi*hi
                    mma16816(acc[mt][nt], ah[mt], blp);   // hi*lo
                    mma16816(acc[mt][nt], al[mt], bhp);   // lo*hi
                }
        }
    }

    // ---- epilogue: bias + relu, padded-pos -> (y,x) with bounds check ----
    #pragma unroll
    for (int mt = 0; mt < 4; mt++) {
        const int r0 = co0 + wm * 64 + mt * 16 + (lane >> 2);
        const float bv0 = brpn[r0];
        const float bv1 = brpn[r0 + 8];
        const size_t fb0 = ((size_t)(bz * IN_CH) + r0) * (HH * WW);
        const size_t fb1 = ((size_t)(bz * IN_CH) + r0 + 8) * (HH * WW);
        #pragma unroll
        for (int nt = 0; nt < 6; nt++) {
            const int p = p0 + wn * 48 + nt * 8 + ((lane & 3) << 1);
            #pragma unroll
            for (int j = 0; j < 2; j++) {
                const int pp = p + j;
                const int yy = pp / PW;
                const int xx = pp - yy * PW;
                if (yy < HH && xx < WW) {
                    const size_t o = (size_t)yy * WW + xx;
                    g_feat[fb0 + o] = fmaxf(acc[mt][nt][0 + j] + bv0, 0.0f);
                    g_feat[fb1 + o] = fmaxf(acc[mt][nt][2 + j] + bv1, 0.0f);
                }
            }
        }
    }
}

// ---------------- 1x1 heads (unchanged from passing R6) ----------------
__global__ __launch_bounds__(256)
void heads_kernel(const float* __restrict__ bcls, const float* __restrict__ bbbox,
                  float* __restrict__ out) {
    __shared__ float sw[128][NHEADP];
    const int idx = blockIdx.x * 256 + threadIdx.x;
    const bool active = idx < BATCH * HH * WW;
    const int b = idx / (HH * WW);
    const int hw = idx % (HH * WW);
    const float* fp = g_feat + (size_t)b * IN_CH * HH * WW + hw;

    float acc[NHEADP];
    #pragma unroll
    for (int c = 0; c < NHEADP; c++) acc[c] = 0.0f;

    for (int ci0 = 0; ci0 < IN_CH; ci0 += 128) {
        __syncthreads();
        for (int e = threadIdx.x; e < 128 * NHEADP; e += 256)
            ((float*)sw)[e] = g_wh[(size_t)ci0 * NHEADP + e];
        __syncthreads();
        if (active) {
            for (int ci = 0; ci < 128; ci++) {
                float v = fp[(size_t)(ci0 + ci) * HH * WW];
                const float4* wr = (const float4*)sw[ci];
                #pragma unroll
                for (int q = 0; q < NHEADP / 4; q++) {
                    float4 w = wr[q];
                    acc[q * 4 + 0] += v * w.x;
                    acc[q * 4 + 1] += v * w.y;
                    acc[q * 4 + 2] += v * w.z;
                    acc[q * 4 + 3] += v * w.w;
                }
            }
        }
    }

    if (active) {
        #pragma unroll
        for (int co = 0; co < NA; co++)
            out[((size_t)(b * NA + co)) * (HH * WW) + hw] = acc[co] + bcls[co];
        float* outb = out + (size_t)BATCH * NA * HH * WW;
        #pragma unroll
        for (int j = 0; j < 36; j++)
            outb[((size_t)(b * 36 + j)) * (HH * WW) + hw] = acc[NA + j] + bbbox[j];
    }
}

// ---------------- launch ----------------
extern "C" void kernel_launch(void* const* d_in, const int* in_sizes, int n_in,
                              void* d_out, int out_size) {
    const float* x      = (const float*)d_in[0];
    const float* w_rpn  = (const float*)d_in[1];
    const float* b_rpn  = (const float*)d_in[2];
    const float* w_cls  = (const float*)d_in[3];
    const float* b_cls  = (const float*)d_in[4];
    const float* w_bbox = (const float*)d_in[5];
    const float* b_bbox = (const float*)d_in[6];
    float* out = (float*)d_out;

    cudaFuncSetAttribute(conv_mma, cudaFuncAttributeMaxDynamicSharedMemorySize, DSMEM_BYTES);

    wsplit_kernel<<<(9 * IN_CH * IN_CH + 255) / 256, 256>>>(w_rpn);
    transform_whead<<<(IN_CH * NHEADP + 255) / 256, 256>>>(w_cls, w_bbox);
    xborder_kernel<<<(BATCH * 404 * IN_CH + 255) / 256, 256>>>();
    xsplit_kernel<<<dim3(4, HH, BATCH), dim3(32, 8)>>>(x);

    conv_mma<<<dim3(IN_CH / BM, NT_PER_B, BATCH), 256, DSMEM_BYTES>>>(b_rpn);

    heads_kernel<<<(BATCH * HH * WW + 255) / 256, 256>>>(b_cls, b_bbox, out);
}

// round 8
// speedup vs baseline: 3.9990x; 1.0379x over previous
#include <cuda_runtime.h>
#include <cuda_bf16.h>
#include <cstdint>

#define IN_CH 512
#define BATCH 8
#define HH 100
#define WW 100
#define NA 9
#define NHEAD 45
#define NHEADP 48
#define NPOSOUT 80000                // BATCH*HH*WW

#define PW 102                       // padded grid width/height
#define NPOS (PW * PW)               // 10404 padded positions per batch
#define BM 128                       // co per CTA
#define BN 192                       // positions per CTA
#define NT_PER_B 55                  // ceil(10404/192)
#define NITER 72                     // 24 (ky,kc) groups * 3 kx
#define NGRP 24                      // 3 ky * 8 ci-chunks
#define XWIN 194                     // BN + 2 rows staged per x window
#define XROWS (BATCH * NPOS + 768)   // slack for shifted tail-tile reads

// smem layout: 3 w buffers + 2 x buffers
#define WBUF_BYTES 32768             // whi 16K + wlo 16K (128 co x 64 ci)
#define XBUF_BYTES 49664             // xhi 24832 + xlo 24832 (194 rows x 128B)
#define OFF_X0 (3 * WBUF_BYTES)      // 98304
#define DSMEM_BYTES (3 * WBUF_BYTES + 2 * XBUF_BYTES)   // 197632 (193KB)

// ---------------- device scratch (allocation-free) ----------------
__device__ float g_feat[BATCH * IN_CH * HH * WW];           // fp32 feature map
__device__ __nv_bfloat16 g_xhi[(size_t)XROWS * IN_CH];      // padded channels-last x, hi
__device__ __nv_bfloat16 g_xlo[(size_t)XROWS * IN_CH];      // lo
__device__ __nv_bfloat16 g_whi[9 * IN_CH * IN_CH];          // weights [k9][co][ci], hi
__device__ __nv_bfloat16 g_wlo[9 * IN_CH * IN_CH];          // lo
__device__ float g_wh[IN_CH * NHEADP];                      // head weights [ci][co48]
__device__ float g_part[4 * NHEAD * NPOSOUT];               // head partials [c][co][pos]

// ---------------- PTX helpers (base sm_80-era features only) ----------------
__device__ __forceinline__ uint32_t smem_u32(const void* p) {
    uint32_t a;
    asm("{ .reg .u64 t; cvta.to.shared.u64 t, %1; cvt.u32.u64 %0, t; }" : "=r"(a) : "l"(p));
    return a;
}
__device__ __forceinline__ void cp16(uint32_t sdst, const void* gsrc) {
    asm volatile("cp.async.cg.shared.global [%0], [%1], 16;" :: "r"(sdst), "l"(gsrc) : "memory");
}
#define CP_COMMIT() asm volatile("cp.async.commit_group;" ::: "memory")
#define CP_WAIT(n)  asm volatile("cp.async.wait_group %0;" :: "n"(n) : "memory")

__device__ __forceinline__ void ldsm4(uint32_t* r, uint32_t addr) {
    asm volatile("ldmatrix.sync.aligned.m8n8.x4.shared.b16 {%0,%1,%2,%3}, [%4];"
        : "=r"(r[0]), "=r"(r[1]), "=r"(r[2]), "=r"(r[3]) : "r"(addr));
}
__device__ __forceinline__ void mma16816(float* d, const uint32_t* a, const uint32_t* b) {
    asm volatile(
        "mma.sync.aligned.m16n8k16.row.col.f32.bf16.bf16.f32 "
        "{%0,%1,%2,%3}, {%4,%5,%6,%7}, {%8,%9}, {%0,%1,%2,%3};"
        : "+f"(d[0]), "+f"(d[1]), "+f"(d[2]), "+f"(d[3])
        : "r"(a[0]), "r"(a[1]), "r"(a[2]), "r"(a[3]), "r"(b[0]), "r"(b[1]));
}
__device__ __forceinline__ uint32_t swz(uint32_t off) { return off ^ ((off >> 3) & 0x70); }

// ---------------- transform kernels (unchanged from passing R7) ----------------
__global__ void wsplit_kernel(const float* __restrict__ w) {
    int idx = blockIdx.x * blockDim.x + threadIdx.x;
    if (idx >= 9 * IN_CH * IN_CH) return;
    int k9 = idx / (IN_CH * IN_CH);
    int rem = idx % (IN_CH * IN_CH);
    int co = rem / IN_CH, ci = rem % IN_CH;
    float v = w[((size_t)co * IN_CH + ci) * 9 + k9];
    __nv_bfloat16 hi = __float2bfloat16(v);
    __nv_bfloat16 lo = __float2bfloat16(v - __bfloat162float(hi));
    g_whi[idx] = hi;                                        // [k9][co][ci]
    g_wlo[idx] = lo;
}

__global__ void xsplit_kernel(const float* __restrict__ x) {
    __shared__ float tile[32][33];
    int xc = blockIdx.x, y = blockIdx.y, b = blockIdx.z;
    int x0 = xc * 32;
    for (int cc0 = 0; cc0 < IN_CH; cc0 += 32) {
        #pragma unroll
        for (int it = 0; it < 4; it++) {
            int ci = cc0 + threadIdx.y + it * 8;
            int xx = x0 + threadIdx.x;
            float v = 0.0f;
            if (xx < WW) v = x[(((size_t)b * IN_CH + ci) * HH + y) * WW + xx];
            tile[threadIdx.y + it * 8][threadIdx.x] = v;
        }
        __syncthreads();
        #pragma unroll
        for (int j = 0; j < 4; j++) {
            int xl = threadIdx.y * 4 + j;
            int xx = x0 + xl;
            if (xx < WW) {
                float v = tile[threadIdx.x][xl];
                __nv_bfloat16 hi = __float2bfloat16(v);
                __nv_bfloat16 lo = __float2bfloat16(v - __bfloat162float(hi));
                size_t row = (size_t)b * NPOS + (size_t)(y + 1) * PW + (xx + 1);
                g_xhi[row * IN_CH + cc0 + threadIdx.x] = hi;
                g_xlo[row * IN_CH + cc0 + threadIdx.x] = lo;
            }
        }
        __syncthreads();
    }
}

__global__ void xborder_kernel() {
    int idx = blockIdx.x * blockDim.x + threadIdx.x;
    if (idx >= BATCH * 404 * IN_CH) return;
    int b = idx / (404 * IN_CH);
    int r = idx % (404 * IN_CH);
    int bp = r / IN_CH, ci = r % IN_CH;
    int p;
    if (bp < 102)       p = bp;
    else if (bp < 204)  p = 101 * PW + (bp - 102);
    else { int q = bp - 204; p = (1 + q / 2) * PW + ((q & 1) ? 101 : 0); }
    size_t e = ((size_t)b * NPOS + p) * IN_CH + ci;
    g_xhi[e] = __float2bfloat16(0.0f);
    g_xlo[e] = __float2bfloat16(0.0f);
}

__global__ void transform_whead(const float* __restrict__ wcls, const float* __restrict__ wbbox) {
    int idx = blockIdx.x * blockDim.x + threadIdx.x;
    if (idx >= IN_CH * NHEADP) return;
    int co = idx % NHEADP, ci = idx / NHEADP;
    float v = 0.0f;
    if (co < NA)         v = wcls[co * IN_CH + ci];
    else if (co < NHEAD) v = wbbox[(co - NA) * IN_CH + ci];
    g_wh[idx] = v;
}

// ---------------- main conv: mma.sync implicit GEMM, PASS-MAJOR mma order ----------------
extern __shared__ char dsm_raw[];

__global__ __launch_bounds__(256, 1)
void conv_mma(const float* __restrict__ brpn) {
    const uint32_t base = smem_u32(dsm_raw);
    const uint32_t xbase = base + OFF_X0;
    const int tid  = threadIdx.x;
    const int lane = tid & 31;
    const int wid  = tid >> 5;
    const int wm   = wid & 1;          // warp co-tile   (2 x 64)
    const int wn   = wid >> 1;         // warp pos-tile  (4 x 48)
    const int co0  = blockIdx.x * BM;
    const int p0   = blockIdx.y * BN;
    const int bz   = blockIdx.z;
    const size_t bbase = (size_t)bz * NPOS;

    float acc[4][6][4];
    #pragma unroll
    for (int mt = 0; mt < 4; mt++)
        #pragma unroll
        for (int nt = 0; nt < 6; nt++)
            #pragma unroll
            for (int i = 0; i < 4; i++) acc[mt][nt][i] = 0.0f;

    // ldmatrix lane-derived constants (identical mapping to verified R6/R7 kernels)
    const int arowoff = lane & 15;
    const int ahalf   = lane >> 4;
    const int browoff = (lane & 7) + ((lane >> 4) << 3);
    const int bhalf   = (lane >> 3) & 1;
    const int l7      = lane & 7;

    uint32_t aoff[4];
    #pragma unroll
    for (int mt = 0; mt < 4; mt++) aoff[mt] = (uint32_t)(wm * 64 + mt * 16 + arowoff) * 128u;

    // ---- staging helpers (unchanged) ----
    auto stage_w = [&](int k9, int kc, uint32_t sb) {
        size_t wrow = (size_t)k9 * IN_CH + co0;
        #pragma unroll
        for (int i = 0; i < 4; i++) {
            int e = i * 256 + tid;
            int rr = e >> 3, cc = e & 7;
            uint32_t so = swz((uint32_t)(rr * 128 + cc * 16));
            size_t go = (wrow + rr) * IN_CH + (size_t)kc * 64 + cc * 8;
            cp16(sb + so, g_whi + go);
            cp16(sb + 16384 + so, g_wlo + go);
        }
    };
    auto stage_x = [&](int ky, int kc, uint32_t sb) {
        size_t xrow = bbase + (size_t)(p0 + ky * PW);
        for (int e = tid; e < XWIN * 8; e += 256) {
            int rr = e >> 3, cc = e & 7;
            uint32_t so = swz((uint32_t)(rr * 128 + cc * 16));
            size_t go = (xrow + rr) * IN_CH + (size_t)kc * 64 + cc * 8;
            cp16(sb + so, g_xhi + go);
            cp16(sb + 24832 + so, g_xlo + go);
        }
    };

    // ---- prologue ----
    stage_x(0, 0, xbase);
    stage_w(0, 0, base);
    CP_COMMIT();
    stage_w(1, 0, base + WBUF_BYTES);
    CP_COMMIT();

    // ---- main loop: iter i -> group g=i/3 (ky=g/8, kc=g%8), offset kx=i%3 ----
    for (int i = 0; i < NITER; i++) {
        const int g  = i / 3;
        const int kx = i - 3 * g;
        CP_WAIT(1);
        __syncthreads();

        {
            if (kx == 1) {
                int gn = g + 1;
                if (gn < NGRP)
                    stage_x(gn >> 3, gn & 7, xbase + (uint32_t)(gn & 1) * XBUF_BYTES);
            }
            int i2 = i + 2;
            if (i2 < NITER) {
                int g2 = i2 / 3;
                stage_w((g2 >> 3) * 3 + (i2 - 3 * g2), g2 & 7,
                        base + (uint32_t)(i2 % 3) * WBUF_BYTES);
            }
            CP_COMMIT();
        }

        const uint32_t wb = base + (uint32_t)(i % 3) * WBUF_BYTES;
        const uint32_t xb = xbase + (uint32_t)(g & 1) * XBUF_BYTES;
        const int l7x = (l7 + kx) & 7;
        const uint32_t brow = (uint32_t)(wn * 48 + browoff + kx) * 128u;

        #pragma unroll
        for (int ks = 0; ks < 4; ks++) {
            const uint32_t acol = (uint32_t)((2 * ks + ahalf) ^ l7) << 4;
            const uint32_t bcol = (uint32_t)((2 * ks + bhalf) ^ l7x) << 4;
            uint32_t ah[4][4], al[4][4], bh[3][4], bl[3][4];
            #pragma unroll
            for (int mt = 0; mt < 4; mt++) {
                ldsm4(ah[mt], wb + aoff[mt] + acol);
                ldsm4(al[mt], wb + 16384 + aoff[mt] + acol);
            }
            #pragma unroll
            for (int np = 0; np < 3; np++) {
                uint32_t ba = xb + brow + (uint32_t)(np * 16) * 128u + bcol;
                ldsm4(bh[np], ba);
                ldsm4(bl[np], ba + 24832);
            }
            // PASS-MAJOR: same-acc reuse spaced 24 independent MMAs apart
            #pragma unroll
            for (int mt = 0; mt < 4; mt++)
                #pragma unroll
                for (int nt = 0; nt < 6; nt++)
                    mma16816(acc[mt][nt], ah[mt], &bh[nt >> 1][(nt & 1) * 2]);   // hi*hi
            #pragma unroll
            for (int mt = 0; mt < 4; mt++)
                #pragma unroll
                for (int nt = 0; nt < 6; nt++)
                    mma16816(acc[mt][nt], ah[mt], &bl[nt >> 1][(nt & 1) * 2]);   // hi*lo
            #pragma unroll
            for (int mt = 0; mt < 4; mt++)
                #pragma unroll
                for (int nt = 0; nt < 6; nt++)
                    mma16816(acc[mt][nt], al[mt], &bh[nt >> 1][(nt & 1) * 2]);   // lo*hi
        }
    }

    // ---- epilogue: bias + relu, padded-pos -> (y,x) with bounds check ----
    #pragma unroll
    for (int mt = 0; mt < 4; mt++) {
        const int r0 = co0 + wm * 64 + mt * 16 + (lane >> 2);
        const float bv0 = brpn[r0];
        const float bv1 = brpn[r0 + 8];
        const size_t fb0 = ((size_t)(bz * IN_CH) + r0) * (HH * WW);
        const size_t fb1 = ((size_t)(bz * IN_CH) + r0 + 8) * (HH * WW);
        #pragma unroll
        for (int nt = 0; nt < 6; nt++) {
            const int p = p0 + wn * 48 + nt * 8 + ((lane & 3) << 1);
            #pragma unroll
            for (int j = 0; j < 2; j++) {
                const int pp = p + j;
                const int yy = pp / PW;
                const int xx = pp - yy * PW;
                if (yy < HH && xx < WW) {
                    const size_t o = (size_t)yy * WW + xx;
                    g_feat[fb0 + o] = fmaxf(acc[mt][nt][0 + j] + bv0, 0.0f);
                    g_feat[fb1 + o] = fmaxf(acc[mt][nt][2 + j] + bv1, 0.0f);
                }
            }
        }
    }
}

// ---------------- heads stage A: ci-split partials (4x parallelism) ----------------
__global__ __launch_bounds__(256)
void headsA_kernel() {
    __shared__ float sw[128][NHEADP];
    const int c = blockIdx.y;                              // ci chunk 0..3
    const int idx = blockIdx.x * 256 + threadIdx.x;        // flat position 0..79999
    const bool active = idx < NPOSOUT;
    const int b = idx / (HH * WW);
    const int hw = idx % (HH * WW);
    const float* fp = g_feat + ((size_t)b * IN_CH + c * 128) * (HH * WW) + hw;

    for (int e = threadIdx.x; e < 128 * NHEADP; e += 256)
        ((float*)sw)[e] = g_wh[(size_t)(c * 128) * NHEADP + e];
    __syncthreads();

    if (!active) return;

    float acc[NHEADP];
    #pragma unroll
    for (int q = 0; q < NHEADP; q++) acc[q] = 0.0f;

    for (int ci = 0; ci < 128; ci++) {
        float v = fp[(size_t)ci * (HH * WW)];
        const float4* wr = (const float4*)sw[ci];
        #pragma unroll
        for (int q = 0; q < NHEADP / 4; q++) {
            float4 w = wr[q];
            acc[q * 4 + 0] += v * w.x;
            acc[q * 4 + 1] += v * w.y;
            acc[q * 4 + 2] += v * w.z;
            acc[q * 4 + 3] += v * w.w;
        }
    }

    // coalesced stores: [c][co][pos]
    #pragma unroll
    for (int co = 0; co < NHEAD; co++)
        g_part[((size_t)(c * NHEAD + co)) * NPOSOUT + idx] = acc[co];
}

// ---------------- heads stage B: reduce 4 partials + bias -> out ----------------
__global__ __launch_bounds__(256)
void headsB_kernel(const float* __restrict__ bcls, const float* __restrict__ bbbox,
                   float* __restrict__ out) {
    const int e = blockIdx.x * 256 + threadIdx.x;
    if (e >= NHEAD * NPOSOUT) return;
    const int co = e / NPOSOUT;
    const int pos = e % NPOSOUT;
    float s = g_part[e]
            + g_part[e + 1 * NHEAD * NPOSOUT]
            + g_part[e + 2 * NHEAD * NPOSOUT]
            + g_part[e + 3 * NHEAD * NPOSOUT];
    const int b = pos / (HH * WW);
    const int hw = pos % (HH * WW);
    if (co < NA) {
        out[((size_t)(b * NA + co)) * (HH * WW) + hw] = s + bcls[co];
    } else {
        const int j = co - NA;
        out[(size_t)BATCH * NA * (HH * WW) + ((size_t)(b * 36 + j)) * (HH * WW) + hw]
            = s + bbbox[j];
    }
}

// ---------------- launch ----------------
extern "C" void kernel_launch(void* const* d_in, const int* in_sizes, int n_in,
                              void* d_out, int out_size) {
    const float* x      = (const float*)d_in[0];
    const float* w_rpn  = (const float*)d_in[1];
    const float* b_rpn  = (const float*)d_in[2];
    const float* w_cls  = (const float*)d_in[3];
    const float* b_cls  = (const float*)d_in[4];
    const float* w_bbox = (const float*)d_in[5];
    const float* b_bbox = (const float*)d_in[6];
    float* out = (float*)d_out;

    cudaFuncSetAttribute(conv_mma, cudaFuncAttributeMaxDynamicSharedMemorySize, DSMEM_BYTES);

    wsplit_kernel<<<(9 * IN_CH * IN_CH + 255) / 256, 256>>>(w_rpn);
    transform_whead<<<(IN_CH * NHEADP + 255) / 256, 256>>>(w_cls, w_bbox);
    xborder_kernel<<<(BATCH * 404 * IN_CH + 255) / 256, 256>>>();
    xsplit_kernel<<<dim3(4, HH, BATCH), dim3(32, 8)>>>(x);

    conv_mma<<<dim3(IN_CH / BM, NT_PER_B, BATCH), 256, DSMEM_BYTES>>>(b_rpn);

    headsA_kernel<<<dim3((NPOSOUT + 255) / 256, 4), 256>>>();
    headsB_kernel<<<(NHEAD * NPOSOUT + 255) / 256, 256>>>(b_cls, b_bbox, out);
}

// round 9
// speedup vs baseline: 4.0077x; 1.0022x over previous
#include <cuda_runtime.h>
#include <cuda_fp16.h>
#include <cstdint>

#define IN_CH 512
#define BATCH 8
#define HH 100
#define WW 100
#define NA 9
#define NHEAD 45
#define NHEADP 48
#define NPOSOUT 80000                // BATCH*HH*WW

#define PW 102                       // padded grid width/height
#define NPOS (PW * PW)               // 10404 padded positions per batch
#define BM 128                       // co per CTA
#define BN 192                       // positions per CTA
#define NT_PER_B 55                  // ceil(10404/192)
#define NITER 72                     // 24 (ky,kc) groups * 3 kx
#define NGRP 24                      // 3 ky * 8 ci-chunks
#define XWIN 194                     // BN + 2 rows staged per x window
#define XROWS (BATCH * NPOS + 768)   // slack for shifted tail-tile reads

// smem layout: 3 w buffers + 2 x buffers
#define WBUF_BYTES 32768             // whi 16K + wlo 16K (128 co x 64 ci)
#define XBUF_BYTES 49664             // xhi 24832 + xlo 24832 (194 rows x 128B)
#define OFF_X0 (3 * WBUF_BYTES)      // 98304
#define DSMEM_BYTES (3 * WBUF_BYTES + 2 * XBUF_BYTES)   // 197632 (193KB)

// ---------------- device scratch (allocation-free) ----------------
__device__ float g_feat[BATCH * IN_CH * HH * WW];           // fp32 feature map
__device__ __half g_xhi[(size_t)XROWS * IN_CH];             // padded channels-last x, hi
__device__ __half g_xlo[(size_t)XROWS * IN_CH];             // lo
__device__ __half g_whi[9 * IN_CH * IN_CH];                 // weights [k9][co][ci], hi
__device__ __half g_wlo[9 * IN_CH * IN_CH];                 // lo
__device__ float g_wh[IN_CH * NHEADP];                      // head weights [ci][co48]
__device__ float g_part[4 * NHEAD * NPOSOUT];               // head partials [c][co][pos]

// ---------------- PTX helpers (base sm_80-era features only) ----------------
__device__ __forceinline__ uint32_t smem_u32(const void* p) {
    uint32_t a;
    asm("{ .reg .u64 t; cvta.to.shared.u64 t, %1; cvt.u32.u64 %0, t; }" : "=r"(a) : "l"(p));
    return a;
}
__device__ __forceinline__ void cp16(uint32_t sdst, const void* gsrc) {
    asm volatile("cp.async.cg.shared.global [%0], [%1], 16;" :: "r"(sdst), "l"(gsrc) : "memory");
}
#define CP_COMMIT() asm volatile("cp.async.commit_group;" ::: "memory")
#define CP_WAIT(n)  asm volatile("cp.async.wait_group %0;" :: "n"(n) : "memory")

__device__ __forceinline__ void ldsm4(uint32_t* r, uint32_t addr) {
    asm volatile("ldmatrix.sync.aligned.m8n8.x4.shared.b16 {%0,%1,%2,%3}, [%4];"
        : "=r"(r[0]), "=r"(r[1]), "=r"(r[2]), "=r"(r[3]) : "r"(addr));
}
// fp16 inputs, fp32 accumulator (main pass)
__device__ __forceinline__ void mma_f32(float* d, const uint32_t* a, const uint32_t* b) {
    asm volatile(
        "mma.sync.aligned.m16n8k16.row.col.f32.f16.f16.f32 "
        "{%0,%1,%2,%3}, {%4,%5,%6,%7}, {%8,%9}, {%0,%1,%2,%3};"
        : "+f"(d[0]), "+f"(d[1]), "+f"(d[2]), "+f"(d[3])
        : "r"(a[0]), "r"(a[1]), "r"(a[2]), "r"(a[3]), "r"(b[0]), "r"(b[1]));
}
// fp16 inputs, fp16 accumulator (correction passes)
__device__ __forceinline__ void mma_f16(uint32_t* d, const uint32_t* a, const uint32_t* b) {
    asm volatile(
        "mma.sync.aligned.m16n8k16.row.col.f16.f16.f16.f16 "
        "{%0,%1}, {%2,%3,%4,%5}, {%6,%7}, {%0,%1};"
        : "+r"(d[0]), "+r"(d[1])
        : "r"(a[0]), "r"(a[1]), "r"(a[2]), "r"(a[3]), "r"(b[0]), "r"(b[1]));
}
__device__ __forceinline__ uint32_t swz(uint32_t off) { return off ^ ((off >> 3) & 0x70); }

// ---------------- transform kernels (fp16 variants of passing R8) ----------------
__global__ void wsplit_kernel(const float* __restrict__ w) {
    int idx = blockIdx.x * blockDim.x + threadIdx.x;
    if (idx >= 9 * IN_CH * IN_CH) return;
    int k9 = idx / (IN_CH * IN_CH);
    int rem = idx % (IN_CH * IN_CH);
    int co = rem / IN_CH, ci = rem % IN_CH;
    float v = w[((size_t)co * IN_CH + ci) * 9 + k9];
    __half hi = __float2half_rn(v);
    __half lo = __float2half_rn(v - __half2float(hi));
    g_whi[idx] = hi;                                        // [k9][co][ci]
    g_wlo[idx] = lo;
}

__global__ void xsplit_kernel(const float* __restrict__ x) {
    __shared__ float tile[32][33];
    int xc = blockIdx.x, y = blockIdx.y, b = blockIdx.z;
    int x0 = xc * 32;
    for (int cc0 = 0; cc0 < IN_CH; cc0 += 32) {
        #pragma unroll
        for (int it = 0; it < 4; it++) {
            int ci = cc0 + threadIdx.y + it * 8;
            int xx = x0 + threadIdx.x;
            float v = 0.0f;
            if (xx < WW) v = x[(((size_t)b * IN_CH + ci) * HH + y) * WW + xx];
            tile[threadIdx.y + it * 8][threadIdx.x] = v;
        }
        __syncthreads();
        #pragma unroll
        for (int j = 0; j < 4; j++) {
            int xl = threadIdx.y * 4 + j;
            int xx = x0 + xl;
            if (xx < WW) {
                float v = tile[threadIdx.x][xl];
                __half hi = __float2half_rn(v);
                __half lo = __float2half_rn(v - __half2float(hi));
                size_t row = (size_t)b * NPOS + (size_t)(y + 1) * PW + (xx + 1);
                g_xhi[row * IN_CH + cc0 + threadIdx.x] = hi;
                g_xlo[row * IN_CH + cc0 + threadIdx.x] = lo;
            }
        }
        __syncthreads();
    }
}

__global__ void xborder_kernel() {
    int idx = blockIdx.x * blockDim.x + threadIdx.x;
    if (idx >= BATCH * 404 * IN_CH) return;
    int b = idx / (404 * IN_CH);
    int r = idx % (404 * IN_CH);
    int bp = r / IN_CH, ci = r % IN_CH;
    int p;
    if (bp < 102)       p = bp;
    else if (bp < 204)  p = 101 * PW + (bp - 102);
    else { int q = bp - 204; p = (1 + q / 2) * PW + ((q & 1) ? 101 : 0); }
    size_t e = ((size_t)b * NPOS + p) * IN_CH + ci;
    g_xhi[e] = __float2half_rn(0.0f);
    g_xlo[e] = __float2half_rn(0.0f);
}

__global__ void transform_whead(const float* __restrict__ wcls, const float* __restrict__ wbbox) {
    int idx = blockIdx.x * blockDim.x + threadIdx.x;
    if (idx >= IN_CH * NHEADP) return;
    int co = idx % NHEADP, ci = idx / NHEADP;
    float v = 0.0f;
    if (co < NA)         v = wcls[co * IN_CH + ci];
    else if (co < NHEAD) v = wbbox[(co - NA) * IN_CH + ci];
    g_wh[idx] = v;
}

// ---------------- main conv: fp16 hi/lo, f32-acc main pass + f16-acc corrections ----------------
extern __shared__ char dsm_raw[];

__global__ __launch_bounds__(256, 1)
void conv_mma(const float* __restrict__ brpn) {
    const uint32_t base = smem_u32(dsm_raw);
    const uint32_t xbase = base + OFF_X0;
    const int tid  = threadIdx.x;
    const int lane = tid & 31;
    const int wid  = tid >> 5;
    const int wm   = wid & 1;          // warp co-tile   (2 x 64)
    const int wn   = wid >> 1;         // warp pos-tile  (4 x 48)
    const int co0  = blockIdx.x * BM;
    const int p0   = blockIdx.y * BN;
    const int bz   = blockIdx.z;
    const size_t bbase = (size_t)bz * NPOS;

    float acc[4][6][4];                // main (hi*hi) fp32 accumulators
    uint32_t cacc[4][6][2];            // correction (hi*lo + lo*hi) f16 accumulators
    #pragma unroll
    for (int mt = 0; mt < 4; mt++)
        #pragma unroll
        for (int nt = 0; nt < 6; nt++) {
            #pragma unroll
            for (int i = 0; i < 4; i++) acc[mt][nt][i] = 0.0f;
            cacc[mt][nt][0] = 0u; cacc[mt][nt][1] = 0u;
        }

    // ldmatrix lane-derived constants (identical mapping to verified R6-R8 kernels)
    const int arowoff = lane & 15;
    const int ahalf   = lane >> 4;
    const int browoff = (lane & 7) + ((lane >> 4) << 3);
    const int bhalf   = (lane >> 3) & 1;
    const int l7      = lane & 7;

    uint32_t aoff[4];
    #pragma unroll
    for (int mt = 0; mt < 4; mt++) aoff[mt] = (uint32_t)(wm * 64 + mt * 16 + arowoff) * 128u;

    // ---- staging helpers (byte-identical layout to R8; only element type changed) ----
    auto stage_w = [&](int k9, int kc, uint32_t sb) {
        size_t wrow = (size_t)k9 * IN_CH + co0;
        #pragma unroll
        for (int i = 0; i < 4; i++) {
            int e = i * 256 + tid;
            int rr = e >> 3, cc = e & 7;
            uint32_t so = swz((uint32_t)(rr * 128 + cc * 16));
            size_t go = (wrow + rr) * IN_CH + (size_t)kc * 64 + cc * 8;
            cp16(sb + so, g_whi + go);
            cp16(sb + 16384 + so, g_wlo + go);
        }
    };
    auto stage_x = [&](int ky, int kc, uint32_t sb) {
        size_t xrow = bbase + (size_t)(p0 + ky * PW);
        for (int e = tid; e < XWIN * 8; e += 256) {
            int rr = e >> 3, cc = e & 7;
            uint32_t so = swz((uint32_t)(rr * 128 + cc * 16));
            size_t go = (xrow + rr) * IN_CH + (size_t)kc * 64 + cc * 8;
            cp16(sb + so, g_xhi + go);
            cp16(sb + 24832 + so, g_xlo + go);
        }
    };

    // ---- prologue ----
    stage_x(0, 0, xbase);
    stage_w(0, 0, base);
    CP_COMMIT();
    stage_w(1, 0, base + WBUF_BYTES);
    CP_COMMIT();

    // ---- main loop: iter i -> group g=i/3 (ky=g/8, kc=g%8), offset kx=i%3 ----
    for (int i = 0; i < NITER; i++) {
        const int g  = i / 3;
        const int kx = i - 3 * g;
        CP_WAIT(1);
        __syncthreads();

        {
            if (kx == 1) {
                int gn = g + 1;
                if (gn < NGRP)
                    stage_x(gn >> 3, gn & 7, xbase + (uint32_t)(gn & 1) * XBUF_BYTES);
            }
            int i2 = i + 2;
            if (i2 < NITER) {
                int g2 = i2 / 3;
                stage_w((g2 >> 3) * 3 + (i2 - 3 * g2), g2 & 7,
                        base + (uint32_t)(i2 % 3) * WBUF_BYTES);
            }
            CP_COMMIT();
        }

        const uint32_t wb = base + (uint32_t)(i % 3) * WBUF_BYTES;
        const uint32_t xb = xbase + (uint32_t)(g & 1) * XBUF_BYTES;
        const int l7x = (l7 + kx) & 7;
        const uint32_t brow = (uint32_t)(wn * 48 + browoff + kx) * 128u;

        #pragma unroll
        for (int ks = 0; ks < 4; ks++) {
            const uint32_t acol = (uint32_t)((2 * ks + ahalf) ^ l7) << 4;
            const uint32_t bcol = (uint32_t)((2 * ks + bhalf) ^ l7x) << 4;
            uint32_t ah[4][4], al[4][4], bh[3][4], bl[3][4];
            #pragma unroll
            for (int mt = 0; mt < 4; mt++) {
                ldsm4(ah[mt], wb + aoff[mt] + acol);
                ldsm4(al[mt], wb + 16384 + aoff[mt] + acol);
            }
            #pragma unroll
            for (int np = 0; np < 3; np++) {
                uint32_t ba = xb + brow + (uint32_t)(np * 16) * 128u + bcol;
                ldsm4(bh[np], ba);
                ldsm4(bl[np], ba + 24832);
            }
            // main pass: hi*hi -> fp32 acc
            #pragma unroll
            for (int mt = 0; mt < 4; mt++)
                #pragma unroll
                for (int nt = 0; nt < 6; nt++)
                    mma_f32(acc[mt][nt], ah[mt], &bh[nt >> 1][(nt & 1) * 2]);
            // correction passes: hi*lo + lo*hi -> f16 acc
            #pragma unroll
            for (int mt = 0; mt < 4; mt++)
                #pragma unroll
                for (int nt = 0; nt < 6; nt++)
                    mma_f16(cacc[mt][nt], ah[mt], &bl[nt >> 1][(nt & 1) * 2]);
            #pragma unroll
            for (int mt = 0; mt < 4; mt++)
                #pragma unroll
                for (int nt = 0; nt < 6; nt++)
                    mma_f16(cacc[mt][nt], al[mt], &bh[nt >> 1][(nt & 1) * 2]);
        }
    }

    // ---- epilogue: fold f16 corrections, bias + relu, bounds-checked stores ----
    #pragma unroll
    for (int mt = 0; mt < 4; mt++) {
        const int r0 = co0 + wm * 64 + mt * 16 + (lane >> 2);
        const float bv0 = brpn[r0];
        const float bv1 = brpn[r0 + 8];
        const size_t fb0 = ((size_t)(bz * IN_CH) + r0) * (HH * WW);
        const size_t fb1 = ((size_t)(bz * IN_CH) + r0 + 8) * (HH * WW);
        #pragma unroll
        for (int nt = 0; nt < 6; nt++) {
            // f16 acc layout: reg0 = {(r,c),(r,c+1)}, reg1 = {(r+8,c),(r+8,c+1)}
            const __half2 c0 = *reinterpret_cast<const __half2*>(&cacc[mt][nt][0]);
            const __half2 c1 = *reinterpret_cast<const __half2*>(&cacc[mt][nt][1]);
            float v0 = acc[mt][nt][0] + __low2float(c0);
            float v1 = acc[mt][nt][1] + __high2float(c0);
            float v2 = acc[mt][nt][2] + __low2float(c1);
            float v3 = acc[mt][nt][3] + __high2float(c1);
            const int p = p0 + wn * 48 + nt * 8 + ((lane & 3) << 1);
            {
                const int yy = p / PW, xx = p - (p / PW) * PW;
                if (yy < HH && xx < WW) {
                    const size_t o = (size_t)yy * WW + xx;
                    g_feat[fb0 + o] = fmaxf(v0 + bv0, 0.0f);
                    g_feat[fb1 + o] = fmaxf(v2 + bv1, 0.0f);
                }
            }
            {
                const int pp = p + 1;
                const int yy = pp / PW, xx = pp - (pp / PW) * PW;
                if (yy < HH && xx < WW) {
                    const size_t o = (size_t)yy * WW + xx;
                    g_feat[fb0 + o] = fmaxf(v1 + bv0, 0.0f);
                    g_feat[fb1 + o] = fmaxf(v3 + bv1, 0.0f);
                }
            }
        }
    }
}

// ---------------- heads stage A: ci-split partials (unchanged from passing R8) ----------------
__global__ __launch_bounds__(256)
void headsA_kernel() {
    __shared__ float sw[128][NHEADP];
    const int c = blockIdx.y;                              // ci chunk 0..3
    const int idx = blockIdx.x * 256 + threadIdx.x;        // flat position
    const bool active = idx < NPOSOUT;
    const int b = idx / (HH * WW);
    const int hw = idx % (HH * WW);
    const float* fp = g_feat + ((size_t)b * IN_CH + c * 128) * (HH * WW) + hw;

    for (int e = threadIdx.x; e < 128 * NHEADP; e += 256)
        ((float*)sw)[e] = g_wh[(size_t)(c * 128) * NHEADP + e];
    __syncthreads();

    if (!active) return;

    float acc[NHEADP];
    #pragma unroll
    for (int q = 0; q < NHEADP; q++) acc[q] = 0.0f;

    for (int ci = 0; ci < 128; ci++) {
        float v = fp[(size_t)ci * (HH * WW)];
        const float4* wr = (const float4*)sw[ci];
        #pragma unroll
        for (int q = 0; q < NHEADP / 4; q++) {
            float4 w = wr[q];
            acc[q * 4 + 0] += v * w.x;
            acc[q * 4 + 1] += v * w.y;
            acc[q * 4 + 2] += v * w.z;
            acc[q * 4 + 3] += v * w.w;
        }
    }

    #pragma unroll
    for (int co = 0; co < NHEAD; co++)
        g_part[((size_t)(c * NHEAD + co)) * NPOSOUT + idx] = acc[co];
}

// ---------------- heads stage B: reduce 4 partials + bias -> out (unchanged) ----------------
__global__ __launch_bounds__(256)
void headsB_kernel(const float* __restrict__ bcls, const float* __restrict__ bbbox,
                   float* __restrict__ out) {
    const int e = blockIdx.x * 256 + threadIdx.x;
    if (e >= NHEAD * NPOSOUT) return;
    const int co = e / NPOSOUT;
    const int pos = e % NPOSOUT;
    float s = g_part[e]
            + g_part[e + 1 * NHEAD * NPOSOUT]
            + g_part[e + 2 * NHEAD * NPOSOUT]
            + g_part[e + 3 * NHEAD * NPOSOUT];
    const int b = pos / (HH * WW);
    const int hw = pos % (HH * WW);
    if (co < NA) {
        out[((size_t)(b * NA + co)) * (HH * WW) + hw] = s + bcls[co];
    } else {
        const int j = co - NA;
        out[(size_t)BATCH * NA * (HH * WW) + ((size_t)(b * 36 + j)) * (HH * WW) + hw]
            = s + bbbox[j];
    }
}

// ---------------- launch ----------------
extern "C" void kernel_launch(void* const* d_in, const int* in_sizes, int n_in,
                              void* d_out, int out_size) {
    const float* x      = (const float*)d_in[0];
    const float* w_rpn  = (const float*)d_in[1];
    const float* b_rpn  = (const float*)d_in[2];
    const float* w_cls  = (const float*)d_in[3];
    const float* b_cls  = (const float*)d_in[4];
    const float* w_bbox = (const float*)d_in[5];
    const float* b_bbox = (const float*)d_in[6];
    float* out = (float*)d_out;

    cudaFuncSetAttribute(conv_mma, cudaFuncAttributeMaxDynamicSharedMemorySize, DSMEM_BYTES);

    wsplit_kernel<<<(9 * IN_CH * IN_CH + 255) / 256, 256>>>(w_rpn);
    transform_whead<<<(IN_CH * NHEADP + 255) / 256, 256>>>(w_cls, w_bbox);
    xborder_kernel<<<(BATCH * 404 * IN_CH + 255) / 256, 256>>>();
    xsplit_kernel<<<dim3(4, HH, BATCH), dim3(32, 8)>>>(x);

    conv_mma<<<dim3(IN_CH / BM, NT_PER_B, BATCH), 256, DSMEM_BYTES>>>(b_rpn);

    headsA_kernel<<<dim3((NPOSOUT + 255) / 256, 4), 256>>>();
    headsB_kernel<<<(NHEAD * NPOSOUT + 255) / 256, 256>>>(b_cls, b_bbox, out);
}

// round 10
// speedup vs baseline: 6.3594x; 1.5868x over previous
#include <cuda_runtime.h>
#include <cuda_fp16.h>
#include <cstdint>

#define IN_CH 512
#define BATCH 8
#define HH 100
#define WW 100
#define NA 9
#define NHEAD 45
#define NHEADP 48
#define NPOSOUT 80000                // BATCH*HH*WW

#define PW 102                       // padded grid width/height
#define NPOS (PW * PW)               // 10404 padded positions per batch
#define TPB 2500                     // 50x50 2x2-output tiles per batch
#define NTILES 20000                 // BATCH * TPB
#define TPAD 20096                   // 157 * 128 (tile-dim padded for staging)
#define NU 16                        // winograd coordinates (4x4)

#define BM 128                       // co per CTA
#define BN 128                       // tiles per CTA
#define TBLK 157                     // ceil(NTILES/BN)
#define NITER 8                      // 512 ci / 64

// smem: 3 stages x (Whi 16K | Wlo 16K | Xhi 16K | Xlo 16K)
#define OFF_WHI 0
#define OFF_WLO 16384
#define OFF_XHI 32768
#define OFF_XLO 49152
#define STAGE_BYTES 65536
#define NSTAGE 3
#define DSMEM_BYTES (NSTAGE * STAGE_BYTES)   // 196608

// ---------------- device scratch (allocation-free) ----------------
__device__ float g_feat[BATCH * IN_CH * HH * WW];               // fp32 feature map
__device__ float g_xpad[(size_t)BATCH * NPOS * IN_CH];          // padded channels-last x (fp32)
__device__ __half g_xthi[(size_t)NU * TPAD * IN_CH];            // winograd input, hi
__device__ __half g_xtlo[(size_t)NU * TPAD * IN_CH];            // lo
__device__ __half g_wthi[(size_t)NU * IN_CH * IN_CH];           // winograd weights [u][co][ci], hi
__device__ __half g_wtlo[(size_t)NU * IN_CH * IN_CH];           // lo
__device__ float g_M[(size_t)NU * IN_CH * TPAD];                // transformed-domain products
__device__ float g_wh[IN_CH * NHEADP];                          // head weights [ci][co48]
__device__ float g_part[4 * NHEAD * NPOSOUT];                   // head partials [c][co][pos]

// ---------------- PTX helpers (base sm_80-era features only) ----------------
__device__ __forceinline__ uint32_t smem_u32(const void* p) {
    uint32_t a;
    asm("{ .reg .u64 t; cvta.to.shared.u64 t, %1; cvt.u32.u64 %0, t; }" : "=r"(a) : "l"(p));
    return a;
}
__device__ __forceinline__ void cp16(uint32_t sdst, const void* gsrc) {
    asm volatile("cp.async.cg.shared.global [%0], [%1], 16;" :: "r"(sdst), "l"(gsrc) : "memory");
}
#define CP_COMMIT() asm volatile("cp.async.commit_group;" ::: "memory")
#define CP_WAIT(n)  asm volatile("cp.async.wait_group %0;" :: "n"(n) : "memory")

__device__ __forceinline__ void ldsm4(uint32_t* r, uint32_t addr) {
    asm volatile("ldmatrix.sync.aligned.m8n8.x4.shared.b16 {%0,%1,%2,%3}, [%4];"
        : "=r"(r[0]), "=r"(r[1]), "=r"(r[2]), "=r"(r[3]) : "r"(addr));
}
__device__ __forceinline__ void mma_f32(float* d, const uint32_t* a, const uint32_t* b) {
    asm volatile(
        "mma.sync.aligned.m16n8k16.row.col.f32.f16.f16.f32 "
        "{%0,%1,%2,%3}, {%4,%5,%6,%7}, {%8,%9}, {%0,%1,%2,%3};"
        : "+f"(d[0]), "+f"(d[1]), "+f"(d[2]), "+f"(d[3])
        : "r"(a[0]), "r"(a[1]), "r"(a[2]), "r"(a[3]), "r"(b[0]), "r"(b[1]));
}
__device__ __forceinline__ void mma_f16(uint32_t* d, const uint32_t* a, const uint32_t* b) {
    asm volatile(
        "mma.sync.aligned.m16n8k16.row.col.f16.f16.f16.f16 "
        "{%0,%1}, {%2,%3,%4,%5}, {%6,%7}, {%0,%1};"
        : "+r"(d[0]), "+r"(d[1])
        : "r"(a[0]), "r"(a[1]), "r"(a[2]), "r"(a[3]), "r"(b[0]), "r"(b[1]));
}
__device__ __forceinline__ uint32_t swz(uint32_t off) { return off ^ ((off >> 3) & 0x70); }

// ---------------- weight winograd transform: Wt = G w G^T, fp16 hi/lo ----------------
__global__ void wt_kernel(const float* __restrict__ w) {
    int idx = blockIdx.x * blockDim.x + threadIdx.x;
    if (idx >= IN_CH * IN_CH) return;
    int co = idx / IN_CH, ci = idx % IN_CH;
    const float* wp = w + (size_t)idx * 9;           // [ky][kx]
    float a[3][3];
    #pragma unroll
    for (int r = 0; r < 3; r++)
        #pragma unroll
        for (int c = 0; c < 3; c++) a[r][c] = wp[r * 3 + c];
    // G over rows: u0=w0, u1=(w0+w1+w2)/2, u2=(w0-w1+w2)/2, u3=w2
    float u[4][3];
    #pragma unroll
    for (int c = 0; c < 3; c++) {
        u[0][c] = a[0][c];
        u[1][c] = 0.5f * (a[0][c] + a[1][c] + a[2][c]);
        u[2][c] = 0.5f * (a[0][c] - a[1][c] + a[2][c]);
        u[3][c] = a[2][c];
    }
    #pragma unroll
    for (int r = 0; r < 4; r++) {
        float t0 = u[r][0], t1 = u[r][1], t2 = u[r][2];
        float v[4] = { t0, 0.5f * (t0 + t1 + t2), 0.5f * (t0 - t1 + t2), t2 };
        #pragma unroll
        for (int s = 0; s < 4; s++) {
            int uu = r * 4 + s;
            __half hi = __float2half_rn(v[s]);
            __half lo = __float2half_rn(v[s] - __half2float(hi));
            size_t o = ((size_t)uu * IN_CH + co) * IN_CH + ci;
            g_wthi[o] = hi;
            g_wtlo[o] = lo;
        }
    }
}

// ---------------- padded channels-last fp32 x ----------------
__global__ void xpad_kernel(const float* __restrict__ x) {
    __shared__ float tile[32][33];
    int xc = blockIdx.x, y = blockIdx.y, b = blockIdx.z;
    int x0 = xc * 32;
    for (int cc0 = 0; cc0 < IN_CH; cc0 += 32) {
        #pragma unroll
        for (int it = 0; it < 4; it++) {
            int ci = cc0 + threadIdx.y + it * 8;
            int xx = x0 + threadIdx.x;
            float v = 0.0f;
            if (xx < WW) v = x[(((size_t)b * IN_CH + ci) * HH + y) * WW + xx];
            tile[threadIdx.y + it * 8][threadIdx.x] = v;
        }
        __syncthreads();
        #pragma unroll
        for (int j = 0; j < 4; j++) {
            int xl = threadIdx.y * 4 + j;
            int xx = x0 + xl;
            if (xx < WW) {
                size_t row = (size_t)b * NPOS + (size_t)(y + 1) * PW + (xx + 1);
                g_xpad[row * IN_CH + cc0 + threadIdx.x] = tile[threadIdx.x][xl];
            }
        }
        __syncthreads();
    }
}

__global__ void xborder_kernel() {
    int idx = blockIdx.x * blockDim.x + threadIdx.x;
    if (idx >= BATCH * 404 * IN_CH) return;
    int b = idx / (404 * IN_CH);
    int r = idx % (404 * IN_CH);
    int bp = r / IN_CH, ci = r % IN_CH;
    int p;
    if (bp < 102)       p = bp;
    else if (bp < 204)  p = 101 * PW + (bp - 102);
    else { int q = bp - 204; p = (1 + q / 2) * PW + ((q & 1) ? 101 : 0); }
    g_xpad[((size_t)b * NPOS + p) * IN_CH + ci] = 0.0f;
}

// ---------------- input winograd transform: Xt = B^T d B, fp16 hi/lo ----------------
// block 256 = 8 tiles x 32 ci-pairs; grid (2500, 8 ci-groups)
__global__ __launch_bounds__(256)
void xt_kernel() {
    const int pair = threadIdx.x & 31;
    const int tl   = threadIdx.x >> 5;
    const int tile = blockIdx.x * 8 + tl;
    const int ci   = blockIdx.y * 64 + pair * 2;
    const int b  = tile / TPB;
    const int t2 = tile - b * TPB;
    const int ty = t2 / 50;
    const int tx = t2 - ty * 50;
    const size_t rbase = (size_t)b * NPOS + (size_t)(2 * ty) * PW + 2 * tx;

    float2 d[4][4];
    #pragma unroll
    for (int r = 0; r < 4; r++)
        #pragma unroll
        for (int c = 0; c < 4; c++)
            d[r][c] = *(const float2*)&g_xpad[(rbase + (size_t)r * PW + c) * IN_CH + ci];

    // B^T d: t0=d0-d2, t1=d1+d2, t2=d2-d1, t3=d1-d3 (componentwise on float2)
    float2 t[4][4];
    #pragma unroll
    for (int c = 0; c < 4; c++) {
        t[0][c] = make_float2(d[0][c].x - d[2][c].x, d[0][c].y - d[2][c].y);
        t[1][c] = make_float2(d[1][c].x + d[2][c].x, d[1][c].y + d[2][c].y);
        t[2][c] = make_float2(d[2][c].x - d[1][c].x, d[2][c].y - d[1][c].y);
        t[3][c] = make_float2(d[1][c].x - d[3][c].x, d[1][c].y - d[3][c].y);
    }
    #pragma unroll
    for (int r = 0; r < 4; r++) {
        float2 v[4];
        v[0] = make_float2(t[r][0].x - t[r][2].x, t[r][0].y - t[r][2].y);
        v[1] = make_float2(t[r][1].x + t[r][2].x, t[r][1].y + t[r][2].y);
        v[2] = make_float2(t[r][2].x - t[r][1].x, t[r][2].y - t[r][1].y);
        v[3] = make_float2(t[r][1].x - t[r][3].x, t[r][1].y - t[r][3].y);
        #pragma unroll
        for (int s = 0; s < 4; s++) {
            int uu = r * 4 + s;
            __half hx = __float2half_rn(v[s].x);
            __half hy = __float2half_rn(v[s].y);
            __half lx = __float2half_rn(v[s].x - __half2float(hx));
            __half ly = __float2half_rn(v[s].y - __half2float(hy));
            size_t o = ((size_t)uu * TPAD + tile) * IN_CH + ci;
            *(__half2*)&g_xthi[o] = __halves2half2(hx, hy);
            *(__half2*)&g_xtlo[o] = __halves2half2(lx, ly);
        }
    }
}

__global__ void transform_whead(const float* __restrict__ wcls, const float* __restrict__ wbbox) {
    int idx = blockIdx.x * blockDim.x + threadIdx.x;
    if (idx >= IN_CH * NHEADP) return;
    int co = idx % NHEADP, ci = idx / NHEADP;
    float v = 0.0f;
    if (co < NA)         v = wcls[co * IN_CH + ci];
    else if (co < NHEAD) v = wbbox[(co - NA) * IN_CH + ci];
    g_wh[idx] = v;
}

// ---------------- winograd-domain GEMM: M[u] = Wt[u] (512x512) @ Xt[u] (512 x tiles) ----------------
extern __shared__ char dsm_raw[];

__global__ __launch_bounds__(256, 1)
void gemm_mma() {
    const uint32_t base = smem_u32(dsm_raw);
    const int tid  = threadIdx.x;
    const int lane = tid & 31;
    const int wid  = tid >> 5;
    const int wm   = wid & 1;          // warp co-tile   (2 x 64)
    const int wn   = wid >> 1;         // warp tile-tile (4 x 32)
    const int co0  = blockIdx.x * BM;
    const int p0   = blockIdx.y * BN;
    const int u    = blockIdx.z;

    float acc[4][4][4];
    uint32_t cacc[4][4][2];
    #pragma unroll
    for (int mt = 0; mt < 4; mt++)
        #pragma unroll
        for (int nt = 0; nt < 4; nt++) {
            #pragma unroll
            for (int i = 0; i < 4; i++) acc[mt][nt][i] = 0.0f;
            cacc[mt][nt][0] = 0u; cacc[mt][nt][1] = 0u;
        }

    // ldmatrix lane-derived constants (verified mapping from R6-R9)
    const int arowoff = lane & 15;
    const int ahalf   = lane >> 4;
    const int browoff = (lane & 7) + ((lane >> 4) << 3);
    const int bhalf   = (lane >> 3) & 1;
    const int l7      = lane & 7;

    uint32_t aoff[4];
    #pragma unroll
    for (int mt = 0; mt < 4; mt++) aoff[mt] = (uint32_t)(wm * 64 + mt * 16 + arowoff) * 128u;
    uint32_t boff[2];
    #pragma unroll
    for (int np = 0; np < 2; np++) boff[np] = (uint32_t)(wn * 32 + np * 16 + browoff) * 128u;

    const __half* whi = g_wthi + (size_t)u * IN_CH * IN_CH;
    const __half* wlo = g_wtlo + (size_t)u * IN_CH * IN_CH;
    const __half* xhi = g_xthi + (size_t)u * TPAD * IN_CH;
    const __half* xlo = g_xtlo + (size_t)u * TPAD * IN_CH;

    auto stage = [&](int kc, uint32_t sb) {
        #pragma unroll
        for (int i = 0; i < 4; i++) {
            int e = i * 256 + tid;                       // 0..1023
            int rr = e >> 3, cc = e & 7;
            uint32_t so = swz((uint32_t)(rr * 128 + cc * 16));
            size_t gw = (size_t)(co0 + rr) * IN_CH + kc * 64 + cc * 8;
            size_t gx = (size_t)(p0 + rr) * IN_CH + kc * 64 + cc * 8;
            cp16(sb + OFF_WHI + so, whi + gw);
            cp16(sb + OFF_WLO + so, wlo + gw);
            cp16(sb + OFF_XHI + so, xhi + gx);
            cp16(sb + OFF_XLO + so, xlo + gx);
        }
        CP_COMMIT();
    };

    stage(0, base);
    stage(1, base + STAGE_BYTES);

    for (int c = 0; c < NITER; c++) {
        if (c + 2 < NITER) { CP_WAIT(1); } else { CP_WAIT(0); }
        __syncthreads();
        if (c + 2 < NITER)
            stage(c + 2, base + (uint32_t)((c + 2) % NSTAGE) * STAGE_BYTES);

        const uint32_t sb = base + (uint32_t)(c % NSTAGE) * STAGE_BYTES;
        #pragma unroll
        for (int ks = 0; ks < 4; ks++) {
            const uint32_t acol = (uint32_t)((2 * ks + ahalf) ^ l7) << 4;
            const uint32_t bcol = (uint32_t)((2 * ks + bhalf) ^ l7) << 4;
            uint32_t ah[4][4], al[4][4], bh[2][4], bl[2][4];
            #pragma unroll
            for (int mt = 0; mt < 4; mt++) {
                ldsm4(ah[mt], sb + OFF_WHI + aoff[mt] + acol);
                ldsm4(al[mt], sb + OFF_WLO + aoff[mt] + acol);
            }
            #pragma unroll
            for (int np = 0; np < 2; np++) {
                ldsm4(bh[np], sb + OFF_XHI + boff[np] + bcol);
                ldsm4(bl[np], sb + OFF_XLO + boff[np] + bcol);
            }
            #pragma unroll
            for (int mt = 0; mt < 4; mt++)
                #pragma unroll
                for (int nt = 0; nt < 4; nt++)
                    mma_f32(acc[mt][nt], ah[mt], &bh[nt >> 1][(nt & 1) * 2]);   // hi*hi
            #pragma unroll
            for (int mt = 0; mt < 4; mt++)
                #pragma unroll
                for (int nt = 0; nt < 4; nt++)
                    mma_f16(cacc[mt][nt], ah[mt], &bl[nt >> 1][(nt & 1) * 2]);  // hi*lo
            #pragma unroll
            for (int mt = 0; mt < 4; mt++)
                #pragma unroll
                for (int nt = 0; nt < 4; nt++)
                    mma_f16(cacc[mt][nt], al[mt], &bh[nt >> 1][(nt & 1) * 2]);  // lo*hi
        }
    }

    // ---- epilogue: fold f16 corrections, store M as float2 (tile pairs) ----
    #pragma unroll
    for (int mt = 0; mt < 4; mt++) {
        const int r0 = co0 + wm * 64 + mt * 16 + (lane >> 2);
        const size_t mb0 = ((size_t)u * IN_CH + r0) * TPAD;
        const size_t mb1 = ((size_t)u * IN_CH + r0 + 8) * TPAD;
        #pragma unroll
        for (int nt = 0; nt < 4; nt++) {
            const __half2 c0 = *reinterpret_cast<const __half2*>(&cacc[mt][nt][0]);
            const __half2 c1 = *reinterpret_cast<const __half2*>(&cacc[mt][nt][1]);
            const int p = p0 + wn * 32 + nt * 8 + ((lane & 3) << 1);
            *(float2*)&g_M[mb0 + p] = make_float2(acc[mt][nt][0] + __low2float(c0),
                                                  acc[mt][nt][1] + __high2float(c0));
            *(float2*)&g_M[mb1 + p] = make_float2(acc[mt][nt][2] + __low2float(c1),
                                                  acc[mt][nt][3] + __high2float(c1));
        }
    }
}

// ---------------- inverse transform: feat = A^T M A + bias, ReLU ----------------
__global__ __launch_bounds__(256)
void inv_kernel(const float* __restrict__ brpn) {
    const int idx = blockIdx.x * 256 + threadIdx.x;
    if (idx >= IN_CH * NTILES) return;
    const int co   = idx / NTILES;
    const int tile = idx - co * NTILES;
    const int b  = tile / TPB;
    const int t2 = tile - b * TPB;
    const int ty = t2 / 50;
    const int tx = t2 - ty * 50;

    float m[4][4];
    #pragma unroll
    for (int r = 0; r < 4; r++)
        #pragma unroll
        for (int s = 0; s < 4; s++)
            m[r][s] = g_M[((size_t)(r * 4 + s) * IN_CH + co) * TPAD + tile];

    // A^T m: t0 = m0+m1+m2, t1 = m1-m2-m3 (per column)
    float t0[4], t1[4];
    #pragma unroll
    for (int s = 0; s < 4; s++) {
        t0[s] = m[0][s] + m[1][s] + m[2][s];
        t1[s] = m[1][s] - m[2][s] - m[3][s];
    }
    const float bv = brpn[co];
    float o00 = t0[0] + t0[1] + t0[2] + bv;
    float o01 = t0[1] - t0[2] - t0[3] + bv;
    float o10 = t1[0] + t1[1] + t1[2] + bv;
    float o11 = t1[1] - t1[2] - t1[3] + bv;

    float* fb = g_feat + ((size_t)(b * IN_CH + co)) * (HH * WW) + (size_t)(2 * ty) * WW + 2 * tx;
    *(float2*)fb        = make_float2(fmaxf(o00, 0.0f), fmaxf(o01, 0.0f));
    *(float2*)(fb + WW) = make_float2(fmaxf(o10, 0.0f), fmaxf(o11, 0.0f));
}

// ---------------- heads stage A/B (unchanged from passing R8/R9) ----------------
__global__ __launch_bounds__(256)
void headsA_kernel() {
    __shared__ float sw[128][NHEADP];
    const int c = blockIdx.y;
    const int idx = blockIdx.x * 256 + threadIdx.x;
    const bool active = idx < NPOSOUT;
    const int b = idx / (HH * WW);
    const int hw = idx % (HH * WW);
    const float* fp = g_feat + ((size_t)b * IN_CH + c * 128) * (HH * WW) + hw;

    for (int e = threadIdx.x; e < 128 * NHEADP; e += 256)
        ((float*)sw)[e] = g_wh[(size_t)(c * 128) * NHEADP + e];
    __syncthreads();

    if (!active) return;

    float acc[NHEADP];
    #pragma unroll
    for (int q = 0; q < NHEADP; q++) acc[q] = 0.0f;

    for (int ci = 0; ci < 128; ci++) {
        float v = fp[(size_t)ci * (HH * WW)];
        const float4* wr = (const float4*)sw[ci];
        #pragma unroll
        for (int q = 0; q < NHEADP / 4; q++) {
            float4 w = wr[q];
            acc[q * 4 + 0] += v * w.x;
            acc[q * 4 + 1] += v * w.y;
            acc[q * 4 + 2] += v * w.z;
            acc[q * 4 + 3] += v * w.w;
        }
    }

    #pragma unroll
    for (int co = 0; co < NHEAD; co++)
        g_part[((size_t)(c * NHEAD + co)) * NPOSOUT + idx] = acc[co];
}

__global__ __launch_bounds__(256)
void headsB_kernel(const float* __restrict__ bcls, const float* __restrict__ bbbox,
                   float* __restrict__ out) {
    const int e = blockIdx.x * 256 + threadIdx.x;
    if (e >= NHEAD * NPOSOUT) return;
    const int co = e / NPOSOUT;
    const int pos = e % NPOSOUT;
    float s = g_part[e]
            + g_part[e + 1 * NHEAD * NPOSOUT]
            + g_part[e + 2 * NHEAD * NPOSOUT]
            + g_part[e + 3 * NHEAD * NPOSOUT];
    const int b = pos / (HH * WW);
    const int hw = pos % (HH * WW);
    if (co < NA) {
        out[((size_t)(b * NA + co)) * (HH * WW) + hw] = s + bcls[co];
    } else {
        const int j = co - NA;
        out[(size_t)BATCH * NA * (HH * WW) + ((size_t)(b * 36 + j)) * (HH * WW) + hw]
            = s + bbbox[j];
    }
}

// ---------------- launch ----------------
extern "C" void kernel_launch(void* const* d_in, const int* in_sizes, int n_in,
                              void* d_out, int out_size) {
    const float* x      = (const float*)d_in[0];
    const float* w_rpn  = (const float*)d_in[1];
    const float* b_rpn  = (const float*)d_in[2];
    const float* w_cls  = (const float*)d_in[3];
    const float* b_cls  = (const float*)d_in[4];
    const float* w_bbox = (const float*)d_in[5];
    const float* b_bbox = (const float*)d_in[6];
    float* out = (float*)d_out;

    cudaFuncSetAttribute(gemm_mma, cudaFuncAttributeMaxDynamicSharedMemorySize, DSMEM_BYTES);

    wt_kernel<<<(IN_CH * IN_CH + 255) / 256, 256>>>(w_rpn);
    transform_whead<<<(IN_CH * NHEADP + 255) / 256, 256>>>(w_cls, w_bbox);
    xborder_kernel<<<(BATCH * 404 * IN_CH + 255) / 256, 256>>>();
    xpad_kernel<<<dim3(4, HH, BATCH), dim3(32, 8)>>>(x);
    xt_kernel<<<dim3(TPB, 8), 256>>>();

    gemm_mma<<<dim3(IN_CH / BM, TBLK, NU), 256, DSMEM_BYTES>>>();

    inv_kernel<<<(IN_CH * NTILES + 255) / 256, 256>>>(b_rpn);

    headsA_kernel<<<dim3((NPOSOUT + 255) / 256, 4), 256>>>();
    headsB_kernel<<<(NHEAD * NPOSOUT + 255) / 256, 256>>>(b_cls, b_bbox, out);
}

// round 11
// speedup vs baseline: 8.6623x; 1.3621x over previous
#include <cuda_runtime.h>
#include <cuda_fp16.h>
#include <cstdint>

#define IN_CH 512
#define BATCH 8
#define HH 100
#define WW 100
#define NA 9
#define NHEAD 45
#define NHEADP 48
#define NPOSOUT 80000                // BATCH*HH*WW

#define PW 102                       // padded grid width/height
#define NPOS (PW * PW)               // 10404 padded positions per batch
#define TPB 2500                     // 50x50 2x2-output tiles per batch
#define NTILES 20000                 // BATCH * TPB
#define TPAD 20096                   // 157 * 128 (tile-dim padded for staging)
#define NU 16                        // winograd coordinates (4x4)

#define BM 128                       // co per CTA
#define BN 128                       // tiles per CTA
#define TBLK 157                     // ceil(NTILES/BN)
#define NITER 8                      // 512 ci / 64

// smem: 3 stages x (Whi 16K | Xhi 16K)
#define OFF_WHI 0
#define OFF_XHI 16384
#define STAGE_BYTES 32768
#define NSTAGE 3
#define DSMEM_BYTES (NSTAGE * STAGE_BYTES)   // 98304

// ---------------- device scratch (allocation-free) ----------------
__device__ float g_feat[BATCH * IN_CH * HH * WW];               // fp32 feature map
__device__ float g_xpad[(size_t)BATCH * NPOS * IN_CH];          // padded channels-last x (fp32)
__device__ __half g_xthi[(size_t)NU * TPAD * IN_CH];            // winograd input (fp16)
__device__ __half g_wthi[(size_t)NU * IN_CH * IN_CH];           // winograd weights [u][co][ci] (fp16)
__device__ float g_M[(size_t)NU * IN_CH * TPAD];                // transformed-domain products
__device__ float g_wh[IN_CH * NHEADP];                          // head weights [ci][co48]
__device__ float g_part[4 * NHEAD * NPOSOUT];                   // head partials [c][co][pos]

// ---------------- PTX helpers (base sm_80-era features only) ----------------
__device__ __forceinline__ uint32_t smem_u32(const void* p) {
    uint32_t a;
    asm("{ .reg .u64 t; cvta.to.shared.u64 t, %1; cvt.u32.u64 %0, t; }" : "=r"(a) : "l"(p));
    return a;
}
__device__ __forceinline__ void cp16(uint32_t sdst, const void* gsrc) {
    asm volatile("cp.async.cg.shared.global [%0], [%1], 16;" :: "r"(sdst), "l"(gsrc) : "memory");
}
#define CP_COMMIT() asm volatile("cp.async.commit_group;" ::: "memory")
#define CP_WAIT(n)  asm volatile("cp.async.wait_group %0;" :: "n"(n) : "memory")

__device__ __forceinline__ void ldsm4(uint32_t* r, uint32_t addr) {
    asm volatile("ldmatrix.sync.aligned.m8n8.x4.shared.b16 {%0,%1,%2,%3}, [%4];"
        : "=r"(r[0]), "=r"(r[1]), "=r"(r[2]), "=r"(r[3]) : "r"(addr));
}
__device__ __forceinline__ void mma_f32(float* d, const uint32_t* a, const uint32_t* b) {
    asm volatile(
        "mma.sync.aligned.m16n8k16.row.col.f32.f16.f16.f32 "
        "{%0,%1,%2,%3}, {%4,%5,%6,%7}, {%8,%9}, {%0,%1,%2,%3};"
        : "+f"(d[0]), "+f"(d[1]), "+f"(d[2]), "+f"(d[3])
        : "r"(a[0]), "r"(a[1]), "r"(a[2]), "r"(a[3]), "r"(b[0]), "r"(b[1]));
}
__device__ __forceinline__ uint32_t swz(uint32_t off) { return off ^ ((off >> 3) & 0x70); }

// ---------------- weight winograd transform: Wt = G w G^T, fp16 ----------------
__global__ void wt_kernel(const float* __restrict__ w) {
    int idx = blockIdx.x * blockDim.x + threadIdx.x;
    if (idx >= IN_CH * IN_CH) return;
    int co = idx / IN_CH, ci = idx % IN_CH;
    const float* wp = w + (size_t)idx * 9;           // [ky][kx]
    float a[3][3];
    #pragma unroll
    for (int r = 0; r < 3; r++)
        #pragma unroll
        for (int c = 0; c < 3; c++) a[r][c] = wp[r * 3 + c];
    float u[4][3];
    #pragma unroll
    for (int c = 0; c < 3; c++) {
        u[0][c] = a[0][c];
        u[1][c] = 0.5f * (a[0][c] + a[1][c] + a[2][c]);
        u[2][c] = 0.5f * (a[0][c] - a[1][c] + a[2][c]);
        u[3][c] = a[2][c];
    }
    #pragma unroll
    for (int r = 0; r < 4; r++) {
        float t0 = u[r][0], t1 = u[r][1], t2 = u[r][2];
        float v[4] = { t0, 0.5f * (t0 + t1 + t2), 0.5f * (t0 - t1 + t2), t2 };
        #pragma unroll
        for (int s = 0; s < 4; s++) {
            int uu = r * 4 + s;
            g_wthi[((size_t)uu * IN_CH + co) * IN_CH + ci] = __float2half_rn(v[s]);
        }
    }
}

// ---------------- padded channels-last fp32 x ----------------
__global__ void xpad_kernel(const float* __restrict__ x) {
    __shared__ float tile[32][33];
    int xc = blockIdx.x, y = blockIdx.y, b = blockIdx.z;
    int x0 = xc * 32;
    for (int cc0 = 0; cc0 < IN_CH; cc0 += 32) {
        #pragma unroll
        for (int it = 0; it < 4; it++) {
            int ci = cc0 + threadIdx.y + it * 8;
            int xx = x0 + threadIdx.x;
            float v = 0.0f;
            if (xx < WW) v = x[(((size_t)b * IN_CH + ci) * HH + y) * WW + xx];
            tile[threadIdx.y + it * 8][threadIdx.x] = v;
        }
        __syncthreads();
        #pragma unroll
        for (int j = 0; j < 4; j++) {
            int xl = threadIdx.y * 4 + j;
            int xx = x0 + xl;
            if (xx < WW) {
                size_t row = (size_t)b * NPOS + (size_t)(y + 1) * PW + (xx + 1);
                g_xpad[row * IN_CH + cc0 + threadIdx.x] = tile[threadIdx.x][xl];
            }
        }
        __syncthreads();
    }
}

__global__ void xborder_kernel() {
    int idx = blockIdx.x * blockDim.x + threadIdx.x;
    if (idx >= BATCH * 404 * IN_CH) return;
    int b = idx / (404 * IN_CH);
    int r = idx % (404 * IN_CH);
    int bp = r / IN_CH, ci = r % IN_CH;
    int p;
    if (bp < 102)       p = bp;
    else if (bp < 204)  p = 101 * PW + (bp - 102);
    else { int q = bp - 204; p = (1 + q / 2) * PW + ((q & 1) ? 101 : 0); }
    g_xpad[((size_t)b * NPOS + p) * IN_CH + ci] = 0.0f;
}

// ---------------- input winograd transform: Xt = B^T d B, fp16 ----------------
// block 256 = 8 tiles x 32 ci-pairs; grid (2500, 8 ci-groups)
__global__ __launch_bounds__(256)
void xt_kernel() {
    const int pair = threadIdx.x & 31;
    const int tl   = threadIdx.x >> 5;
    const int tile = blockIdx.x * 8 + tl;
    const int ci   = blockIdx.y * 64 + pair * 2;
    const int b  = tile / TPB;
    const int t2 = tile - b * TPB;
    const int ty = t2 / 50;
    const int tx = t2 - ty * 50;
    const size_t rbase = (size_t)b * NPOS + (size_t)(2 * ty) * PW + 2 * tx;

    float2 d[4][4];
    #pragma unroll
    for (int r = 0; r < 4; r++)
        #pragma unroll
        for (int c = 0; c < 4; c++)
            d[r][c] = *(const float2*)&g_xpad[(rbase + (size_t)r * PW + c) * IN_CH + ci];

    float2 t[4][4];
    #pragma unroll
    for (int c = 0; c < 4; c++) {
        t[0][c] = make_float2(d[0][c].x - d[2][c].x, d[0][c].y - d[2][c].y);
        t[1][c] = make_float2(d[1][c].x + d[2][c].x, d[1][c].y + d[2][c].y);
        t[2][c] = make_float2(d[2][c].x - d[1][c].x, d[2][c].y - d[1][c].y);
        t[3][c] = make_float2(d[1][c].x - d[3][c].x, d[1][c].y - d[3][c].y);
    }
    #pragma unroll
    for (int r = 0; r < 4; r++) {
        float2 v[4];
        v[0] = make_float2(t[r][0].x - t[r][2].x, t[r][0].y - t[r][2].y);
        v[1] = make_float2(t[r][1].x + t[r][2].x, t[r][1].y + t[r][2].y);
        v[2] = make_float2(t[r][2].x - t[r][1].x, t[r][2].y - t[r][1].y);
        v[3] = make_float2(t[r][1].x - t[r][3].x, t[r][1].y - t[r][3].y);
        #pragma unroll
        for (int s = 0; s < 4; s++) {
            int uu = r * 4 + s;
            size_t o = ((size_t)uu * TPAD + tile) * IN_CH + ci;
            *(__half2*)&g_xthi[o] =
                __halves2half2(__float2half_rn(v[s].x), __float2half_rn(v[s].y));
        }
    }
}

__global__ void transform_whead(const float* __restrict__ wcls, const float* __restrict__ wbbox) {
    int idx = blockIdx.x * blockDim.x + threadIdx.x;
    if (idx >= IN_CH * NHEADP) return;
    int co = idx % NHEADP, ci = idx / NHEADP;
    float v = 0.0f;
    if (co < NA)         v = wcls[co * IN_CH + ci];
    else if (co < NHEAD) v = wbbox[(co - NA) * IN_CH + ci];
    g_wh[idx] = v;
}

// ---------------- winograd-domain GEMM: M[u] = Wt[u] @ Xt[u], single fp16 pass ----------------
extern __shared__ char dsm_raw[];

__global__ __launch_bounds__(256, 2)
void gemm_mma() {
    const uint32_t base = smem_u32(dsm_raw);
    const int tid  = threadIdx.x;
    const int lane = tid & 31;
    const int wid  = tid >> 5;
    const int wm   = wid & 1;          // warp co-tile   (2 x 64)
    const int wn   = wid >> 1;         // warp tile-tile (4 x 32)
    const int co0  = blockIdx.x * BM;
    const int p0   = blockIdx.y * BN;
    const int u    = blockIdx.z;

    float acc[4][4][4];
    #pragma unroll
    for (int mt = 0; mt < 4; mt++)
        #pragma unroll
        for (int nt = 0; nt < 4; nt++)
            #pragma unroll
            for (int i = 0; i < 4; i++) acc[mt][nt][i] = 0.0f;

    // ldmatrix lane-derived constants (verified mapping from R6-R10)
    const int arowoff = lane & 15;
    const int ahalf   = lane >> 4;
    const int browoff = (lane & 7) + ((lane >> 4) << 3);
    const int bhalf   = (lane >> 3) & 1;
    const int l7      = lane & 7;

    uint32_t aoff[4];
    #pragma unroll
    for (int mt = 0; mt < 4; mt++) aoff[mt] = (uint32_t)(wm * 64 + mt * 16 + arowoff) * 128u;
    uint32_t boff[2];
    #pragma unroll
    for (int np = 0; np < 2; np++) boff[np] = (uint32_t)(wn * 32 + np * 16 + browoff) * 128u;

    const __half* whi = g_wthi + (size_t)u * IN_CH * IN_CH;
    const __half* xhi = g_xthi + (size_t)u * TPAD * IN_CH;

    auto stage = [&](int kc, uint32_t sb) {
        #pragma unroll
        for (int i = 0; i < 4; i++) {
            int e = i * 256 + tid;                       // 0..1023
            int rr = e >> 3, cc = e & 7;
            uint32_t so = swz((uint32_t)(rr * 128 + cc * 16));
            size_t gw = (size_t)(co0 + rr) * IN_CH + kc * 64 + cc * 8;
            size_t gx = (size_t)(p0 + rr) * IN_CH + kc * 64 + cc * 8;
            cp16(sb + OFF_WHI + so, whi + gw);
            cp16(sb + OFF_XHI + so, xhi + gx);
        }
        CP_COMMIT();
    };

    stage(0, base);
    stage(1, base + STAGE_BYTES);

    for (int c = 0; c < NITER; c++) {
        if (c + 2 < NITER) { CP_WAIT(1); } else { CP_WAIT(0); }
        __syncthreads();
        if (c + 2 < NITER)
            stage(c + 2, base + (uint32_t)((c + 2) % NSTAGE) * STAGE_BYTES);

        const uint32_t sb = base + (uint32_t)(c % NSTAGE) * STAGE_BYTES;
        #pragma unroll
        for (int ks = 0; ks < 4; ks++) {
            const uint32_t acol = (uint32_t)((2 * ks + ahalf) ^ l7) << 4;
            const uint32_t bcol = (uint32_t)((2 * ks + bhalf) ^ l7) << 4;
            uint32_t ah[4][4], bh[2][4];
            #pragma unroll
            for (int mt = 0; mt < 4; mt++)
                ldsm4(ah[mt], sb + OFF_WHI + aoff[mt] + acol);
            #pragma unroll
            for (int np = 0; np < 2; np++)
                ldsm4(bh[np], sb + OFF_XHI + boff[np] + bcol);
            #pragma unroll
            for (int mt = 0; mt < 4; mt++)
                #pragma unroll
                for (int nt = 0; nt < 4; nt++)
                    mma_f32(acc[mt][nt], ah[mt], &bh[nt >> 1][(nt & 1) * 2]);
        }
    }

    // ---- epilogue: store M as float2 (tile pairs) ----
    #pragma unroll
    for (int mt = 0; mt < 4; mt++) {
        const int r0 = co0 + wm * 64 + mt * 16 + (lane >> 2);
        const size_t mb0 = ((size_t)u * IN_CH + r0) * TPAD;
        const size_t mb1 = ((size_t)u * IN_CH + r0 + 8) * TPAD;
        #pragma unroll
        for (int nt = 0; nt < 4; nt++) {
            const int p = p0 + wn * 32 + nt * 8 + ((lane & 3) << 1);
            *(float2*)&g_M[mb0 + p] = make_float2(acc[mt][nt][0], acc[mt][nt][1]);
            *(float2*)&g_M[mb1 + p] = make_float2(acc[mt][nt][2], acc[mt][nt][3]);
        }
    }
}

// ---------------- inverse transform: feat = A^T M A + bias, ReLU ----------------
__global__ __launch_bounds__(256)
void inv_kernel(const float* __restrict__ brpn) {
    const int idx = blockIdx.x * 256 + threadIdx.x;
    if (idx >= IN_CH * NTILES) return;
    const int co   = idx / NTILES;
    const int tile = idx - co * NTILES;
    const int b  = tile / TPB;
    const int t2 = tile - b * TPB;
    const int ty = t2 / 50;
    const int tx = t2 - ty * 50;

    float m[4][4];
    #pragma unroll
    for (int r = 0; r < 4; r++)
        #pragma unroll
        for (int s = 0; s < 4; s++)
            m[r][s] = g_M[((size_t)(r * 4 + s) * IN_CH + co) * TPAD + tile];

    float t0[4], t1[4];
    #pragma unroll
    for (int s = 0; s < 4; s++) {
        t0[s] = m[0][s] + m[1][s] + m[2][s];
        t1[s] = m[1][s] - m[2][s] - m[3][s];
    }
    const float bv = brpn[co];
    float o00 = t0[0] + t0[1] + t0[2] + bv;
    float o01 = t0[1] - t0[2] - t0[3] + bv;
    float o10 = t1[0] + t1[1] + t1[2] + bv;
    float o11 = t1[1] - t1[2] - t1[3] + bv;

    float* fb = g_feat + ((size_t)(b * IN_CH + co)) * (HH * WW) + (size_t)(2 * ty) * WW + 2 * tx;
    *(float2*)fb        = make_float2(fmaxf(o00, 0.0f), fmaxf(o01, 0.0f));
    *(float2*)(fb + WW) = make_float2(fmaxf(o10, 0.0f), fmaxf(o11, 0.0f));
}

// ---------------- heads stage A/B (unchanged from passing R8-R10) ----------------
__global__ __launch_bounds__(256)
void headsA_kernel() {
    __shared__ float sw[128][NHEADP];
    const int c = blockIdx.y;
    const int idx = blockIdx.x * 256 + threadIdx.x;
    const bool active = idx < NPOSOUT;
    const int b = idx / (HH * WW);
    const int hw = idx % (HH * WW);
    const float* fp = g_feat + ((size_t)b * IN_CH + c * 128) * (HH * WW) + hw;

    for (int e = threadIdx.x; e < 128 * NHEADP; e += 256)
        ((float*)sw)[e] = g_wh[(size_t)(c * 128) * NHEADP + e];
    __syncthreads();

    if (!active) return;

    float acc[NHEADP];
    #pragma unroll
    for (int q = 0; q < NHEADP; q++) acc[q] = 0.0f;

    for (int ci = 0; ci < 128; ci++) {
        float v = fp[(size_t)ci * (HH * WW)];
        const float4* wr = (const float4*)sw[ci];
        #pragma unroll
        for (int q = 0; q < NHEADP / 4; q++) {
            float4 w = wr[q];
            acc[q * 4 + 0] += v * w.x;
            acc[q * 4 + 1] += v * w.y;
            acc[q * 4 + 2] += v * w.z;
            acc[q * 4 + 3] += v * w.w;
        }
    }

    #pragma unroll
    for (int co = 0; co < NHEAD; co++)
        g_part[((size_t)(c * NHEAD + co)) * NPOSOUT + idx] = acc[co];
}

__global__ __launch_bounds__(256)
void headsB_kernel(const float* __restrict__ bcls, const float* __restrict__ bbbox,
                   float* __restrict__ out) {
    const int e = blockIdx.x * 256 + threadIdx.x;
    if (e >= NHEAD * NPOSOUT) return;
    const int co = e / NPOSOUT;
    const int pos = e % NPOSOUT;
    float s = g_part[e]
            + g_part[e + 1 * NHEAD * NPOSOUT]
            + g_part[e + 2 * NHEAD * NPOSOUT]
            + g_part[e + 3 * NHEAD * NPOSOUT];
    const int b = pos / (HH * WW);
    const int hw = pos % (HH * WW);
    if (co < NA) {
        out[((size_t)(b * NA + co)) * (HH * WW) + hw] = s + bcls[co];
    } else {
        const int j = co - NA;
        out[(size_t)BATCH * NA * (HH * WW) + ((size_t)(b * 36 + j)) * (HH * WW) + hw]
            = s + bbbox[j];
    }
}

// ---------------- launch ----------------
extern "C" void kernel_launch(void* const* d_in, const int* in_sizes, int n_in,
                              void* d_out, int out_size) {
    const float* x      = (const float*)d_in[0];
    const float* w_rpn  = (const float*)d_in[1];
    const float* b_rpn  = (const float*)d_in[2];
    const float* w_cls  = (const float*)d_in[3];
    const float* b_cls  = (const float*)d_in[4];
    const float* w_bbox = (const float*)d_in[5];
    const float* b_bbox = (const float*)d_in[6];
    float* out = (float*)d_out;

    cudaFuncSetAttribute(gemm_mma, cudaFuncAttributeMaxDynamicSharedMemorySize, DSMEM_BYTES);

    wt_kernel<<<(IN_CH * IN_CH + 255) / 256, 256>>>(w_rpn);
    transform_whead<<<(IN_CH * NHEADP + 255) / 256, 256>>>(w_cls, w_bbox);
    xborder_kernel<<<(BATCH * 404 * IN_CH + 255) / 256, 256>>>();
    xpad_kernel<<<dim3(4, HH, BATCH), dim3(32, 8)>>>(x);
    xt_kernel<<<dim3(TPB, 8), 256>>>();

    gemm_mma<<<dim3(IN_CH / BM, TBLK, NU), 256, DSMEM_BYTES>>>();

    inv_kernel<<<(IN_CH * NTILES + 255) / 256, 256>>>(b_rpn);

    headsA_kernel<<<dim3((NPOSOUT + 255) / 256, 4), 256>>>();
    headsB_kernel<<<(NHEAD * NPOSOUT + 255) / 256, 256>>>(b_cls, b_bbox, out);
}

// round 12
// speedup vs baseline: 11.8415x; 1.3670x over previous
#include <cuda_runtime.h>
#include <cuda_fp16.h>
#include <cstdint>

#define IN_CH 512
#define BATCH 8
#define HH 100
#define WW 100
#define NA 9
#define NHEAD 45
#define NHEADP 48
#define NPOSOUT 80000                // BATCH*HH*WW

#define PW 102                       // padded grid width/height
#define NPOS (PW * PW)               // 10404 padded positions per batch
#define TPB 2500                     // 50x50 2x2-output tiles per batch
#define NTILES 20000                 // BATCH * TPB
#define TPAD 20096                   // 157 * 128 (tile-dim padded for staging)
#define NU 16                        // winograd coordinates (4x4)

#define BM 128                       // co per CTA
#define BN 128                       // tiles per CTA
#define TBLK 157                     // ceil(NTILES/BN)
#define NITER 8                      // 512 ci / 64

// smem: 3 stages x (Whi 16K | Xhi 16K)
#define OFF_WHI 0
#define OFF_XHI 16384
#define STAGE_BYTES 32768
#define NSTAGE 3
#define DSMEM_BYTES (NSTAGE * STAGE_BYTES)   // 98304

// ---------------- device scratch (allocation-free) ----------------
__device__ float g_feat[BATCH * IN_CH * HH * WW];               // fp32 feature map
__device__ float g_xpad[(size_t)BATCH * NPOS * IN_CH];          // padded channels-last x (fp32)
__device__ __half g_xthi[(size_t)NU * TPAD * IN_CH];            // winograd input (fp16)
__device__ __half g_wthi[(size_t)NU * IN_CH * IN_CH];           // winograd weights [u][co][ci] (fp16)
__device__ float g_M[(size_t)NU * IN_CH * TPAD];                // transformed-domain products
__device__ float g_wh[IN_CH * NHEADP];                          // head weights [ci][co48]
__device__ float g_part[4 * NHEAD * NPOSOUT];                   // head partials [c][co][pos]

// ---------------- PTX helpers ----------------
__device__ __forceinline__ uint32_t smem_u32(const void* p) {
    uint32_t a;
    asm("{ .reg .u64 t; cvta.to.shared.u64 t, %1; cvt.u32.u64 %0, t; }" : "=r"(a) : "l"(p));
    return a;
}
__device__ __forceinline__ void cp16(uint32_t sdst, const void* gsrc) {
    asm volatile("cp.async.cg.shared.global [%0], [%1], 16;" :: "r"(sdst), "l"(gsrc) : "memory");
}
#define CP_COMMIT() asm volatile("cp.async.commit_group;" ::: "memory")
#define CP_WAIT(n)  asm volatile("cp.async.wait_group %0;" :: "n"(n) : "memory")

__device__ __forceinline__ void ldsm4(uint32_t* r, uint32_t addr) {
    asm volatile("ldmatrix.sync.aligned.m8n8.x4.shared.b16 {%0,%1,%2,%3}, [%4];"
        : "=r"(r[0]), "=r"(r[1]), "=r"(r[2]), "=r"(r[3]) : "r"(addr));
}
__device__ __forceinline__ void mma_f32(float* d, const uint32_t* a, const uint32_t* b) {
    asm volatile(
        "mma.sync.aligned.m16n8k16.row.col.f32.f16.f16.f32 "
        "{%0,%1,%2,%3}, {%4,%5,%6,%7}, {%8,%9}, {%0,%1,%2,%3};"
        : "+f"(d[0]), "+f"(d[1]), "+f"(d[2]), "+f"(d[3])
        : "r"(a[0]), "r"(a[1]), "r"(a[2]), "r"(a[3]), "r"(b[0]), "r"(b[1]));
}
__device__ __forceinline__ uint32_t swz(uint32_t off) { return off ^ ((off >> 3) & 0x70); }

// packed fp32x2 (verified in R2)
__device__ __forceinline__ unsigned long long pk2(float x, float y) {
    unsigned long long r;
    asm("mov.b64 %0, {%1, %2};" : "=l"(r) : "r"(__float_as_int(x)), "r"(__float_as_int(y)));
    return r;
}
__device__ __forceinline__ void upk2(unsigned long long v, float& x, float& y) {
    int a, b;
    asm("mov.b64 {%0, %1}, %2;" : "=r"(a), "=r"(b) : "l"(v));
    x = __int_as_float(a); y = __int_as_float(b);
}
__device__ __forceinline__ void fma2(unsigned long long& d, unsigned long long a, unsigned long long b) {
    asm("fma.rn.f32x2 %0, %1, %2, %0;" : "+l"(d) : "l"(a), "l"(b));
}

// ---------------- weight winograd transform: Wt = G w G^T, fp16 ----------------
__global__ void wt_kernel(const float* __restrict__ w) {
    int idx = blockIdx.x * blockDim.x + threadIdx.x;
    if (idx >= IN_CH * IN_CH) return;
    int co = idx / IN_CH, ci = idx % IN_CH;
    const float* wp = w + (size_t)idx * 9;           // [ky][kx]
    float a[3][3];
    #pragma unroll
    for (int r = 0; r < 3; r++)
        #pragma unroll
        for (int c = 0; c < 3; c++) a[r][c] = wp[r * 3 + c];
    float u[4][3];
    #pragma unroll
    for (int c = 0; c < 3; c++) {
        u[0][c] = a[0][c];
        u[1][c] = 0.5f * (a[0][c] + a[1][c] + a[2][c]);
        u[2][c] = 0.5f * (a[0][c] - a[1][c] + a[2][c]);
        u[3][c] = a[2][c];
    }
    #pragma unroll
    for (int r = 0; r < 4; r++) {
        float t0 = u[r][0], t1 = u[r][1], t2 = u[r][2];
        float v[4] = { t0, 0.5f * (t0 + t1 + t2), 0.5f * (t0 - t1 + t2), t2 };
        #pragma unroll
        for (int s = 0; s < 4; s++) {
            int uu = r * 4 + s;
            g_wthi[((size_t)uu * IN_CH + co) * IN_CH + ci] = __float2half_rn(v[s]);
        }
    }
}

// ---------------- padded channels-last fp32 x (unchanged from R11) ----------------
__global__ void xpad_kernel(const float* __restrict__ x) {
    __shared__ float tile[32][33];
    int xc = blockIdx.x, y = blockIdx.y, b = blockIdx.z;
    int x0 = xc * 32;
    for (int cc0 = 0; cc0 < IN_CH; cc0 += 32) {
        #pragma unroll
        for (int it = 0; it < 4; it++) {
            int ci = cc0 + threadIdx.y + it * 8;
            int xx = x0 + threadIdx.x;
            float v = 0.0f;
            if (xx < WW) v = x[(((size_t)b * IN_CH + ci) * HH + y) * WW + xx];
            tile[threadIdx.y + it * 8][threadIdx.x] = v;
        }
        __syncthreads();
        #pragma unroll
        for (int j = 0; j < 4; j++) {
            int xl = threadIdx.y * 4 + j;
            int xx = x0 + xl;
            if (xx < WW) {
                size_t row = (size_t)b * NPOS + (size_t)(y + 1) * PW + (xx + 1);
                g_xpad[row * IN_CH + cc0 + threadIdx.x] = tile[threadIdx.x][xl];
            }
        }
        __syncthreads();
    }
}

__global__ void xborder_kernel() {
    int idx = blockIdx.x * blockDim.x + threadIdx.x;
    if (idx >= BATCH * 404 * IN_CH) return;
    int b = idx / (404 * IN_CH);
    int r = idx % (404 * IN_CH);
    int bp = r / IN_CH, ci = r % IN_CH;
    int p;
    if (bp < 102)       p = bp;
    else if (bp < 204)  p = 101 * PW + (bp - 102);
    else { int q = bp - 204; p = (1 + q / 2) * PW + ((q & 1) ? 101 : 0); }
    g_xpad[((size_t)b * NPOS + p) * IN_CH + ci] = 0.0f;
}

// ---------------- input winograd transform: rolling 4-row window over ty ----------------
// grid (50 tx, 5 ty-segments, 8 b), block 256 = ci-pairs (512 ci)
__global__ __launch_bounds__(256)
void xt_kernel() {
    const int ci  = threadIdx.x * 2;
    const int tx  = blockIdx.x;
    const int seg = blockIdx.y;
    const int b   = blockIdx.z;
    const size_t base = ((size_t)b * NPOS + 2 * tx) * IN_CH + ci;

    float2 d[4][4];
    // prologue: padded rows 20*seg, 20*seg+1 -> d[2], d[3]
    #pragma unroll
    for (int rr = 0; rr < 2; rr++)
        #pragma unroll
        for (int c = 0; c < 4; c++)
            d[2 + rr][c] = *(const float2*)&g_xpad[base + ((size_t)(seg * 20 + rr) * PW + c) * IN_CH];

    for (int j = 0; j < 10; j++) {
        const int ty = seg * 10 + j;
        #pragma unroll
        for (int c = 0; c < 4; c++) { d[0][c] = d[2][c]; d[1][c] = d[3][c]; }
        #pragma unroll
        for (int rr = 0; rr < 2; rr++)
            #pragma unroll
            for (int c = 0; c < 4; c++)
                d[2 + rr][c] = *(const float2*)&g_xpad[base + ((size_t)(2 * ty + 2 + rr) * PW + c) * IN_CH];

        // B^T d B (identical fp32 ops/order to R11's verified xt)
        float2 t[4][4];
        #pragma unroll
        for (int c = 0; c < 4; c++) {
            t[0][c] = make_float2(d[0][c].x - d[2][c].x, d[0][c].y - d[2][c].y);
            t[1][c] = make_float2(d[1][c].x + d[2][c].x, d[1][c].y + d[2][c].y);
            t[2][c] = make_float2(d[2][c].x - d[1][c].x, d[2][c].y - d[1][c].y);
            t[3][c] = make_float2(d[1][c].x - d[3][c].x, d[1][c].y - d[3][c].y);
        }
        const int tile = b * TPB + ty * 50 + tx;
        #pragma unroll
        for (int r = 0; r < 4; r++) {
            float2 v[4];
            v[0] = make_float2(t[r][0].x - t[r][2].x, t[r][0].y - t[r][2].y);
            v[1] = make_float2(t[r][1].x + t[r][2].x, t[r][1].y + t[r][2].y);
            v[2] = make_float2(t[r][2].x - t[r][1].x, t[r][2].y - t[r][1].y);
            v[3] = make_float2(t[r][1].x - t[r][3].x, t[r][1].y - t[r][3].y);
            #pragma unroll
            for (int s = 0; s < 4; s++) {
                int uu = r * 4 + s;
                size_t o = ((size_t)uu * TPAD + tile) * IN_CH + ci;
                *(__half2*)&g_xthi[o] =
                    __halves2half2(__float2half_rn(v[s].x), __float2half_rn(v[s].y));
            }
        }
    }
}

__global__ void transform_whead(const float* __restrict__ wcls, const float* __restrict__ wbbox) {
    int idx = blockIdx.x * blockDim.x + threadIdx.x;
    if (idx >= IN_CH * NHEADP) return;
    int co = idx % NHEADP, ci = idx / NHEADP;
    float v = 0.0f;
    if (co < NA)         v = wcls[co * IN_CH + ci];
    else if (co < NHEAD) v = wbbox[(co - NA) * IN_CH + ci];
    g_wh[idx] = v;
}

// ---------------- winograd-domain GEMM (unchanged from passing R11) ----------------
extern __shared__ char dsm_raw[];

__global__ __launch_bounds__(256, 2)
void gemm_mma() {
    const uint32_t base = smem_u32(dsm_raw);
    const int tid  = threadIdx.x;
    const int lane = tid & 31;
    const int wid  = tid >> 5;
    const int wm   = wid & 1;
    const int wn   = wid >> 1;
    const int co0  = blockIdx.x * BM;
    const int p0   = blockIdx.y * BN;
    const int u    = blockIdx.z;

    float acc[4][4][4];
    #pragma unroll
    for (int mt = 0; mt < 4; mt++)
        #pragma unroll
        for (int nt = 0; nt < 4; nt++)
            #pragma unroll
            for (int i = 0; i < 4; i++) acc[mt][nt][i] = 0.0f;

    const int arowoff = lane & 15;
    const int ahalf   = lane >> 4;
    const int browoff = (lane & 7) + ((lane >> 4) << 3);
    const int bhalf   = (lane >> 3) & 1;
    const int l7      = lane & 7;

    uint32_t aoff[4];
    #pragma unroll
    for (int mt = 0; mt < 4; mt++) aoff[mt] = (uint32_t)(wm * 64 + mt * 16 + arowoff) * 128u;
    uint32_t boff[2];
    #pragma unroll
    for (int np = 0; np < 2; np++) boff[np] = (uint32_t)(wn * 32 + np * 16 + browoff) * 128u;

    const __half* whi = g_wthi + (size_t)u * IN_CH * IN_CH;
    const __half* xhi = g_xthi + (size_t)u * TPAD * IN_CH;

    auto stage = [&](int kc, uint32_t sb) {
        #pragma unroll
        for (int i = 0; i < 4; i++) {
            int e = i * 256 + tid;
            int rr = e >> 3, cc = e & 7;
            uint32_t so = swz((uint32_t)(rr * 128 + cc * 16));
            size_t gw = (size_t)(co0 + rr) * IN_CH + kc * 64 + cc * 8;
            size_t gx = (size_t)(p0 + rr) * IN_CH + kc * 64 + cc * 8;
            cp16(sb + OFF_WHI + so, whi + gw);
            cp16(sb + OFF_XHI + so, xhi + gx);
        }
        CP_COMMIT();
    };

    stage(0, base);
    stage(1, base + STAGE_BYTES);

    for (int c = 0; c < NITER; c++) {
        if (c + 2 < NITER) { CP_WAIT(1); } else { CP_WAIT(0); }
        __syncthreads();
        if (c + 2 < NITER)
            stage(c + 2, base + (uint32_t)((c + 2) % NSTAGE) * STAGE_BYTES);

        const uint32_t sb = base + (uint32_t)(c % NSTAGE) * STAGE_BYTES;
        #pragma unroll
        for (int ks = 0; ks < 4; ks++) {
            const uint32_t acol = (uint32_t)((2 * ks + ahalf) ^ l7) << 4;
            const uint32_t bcol = (uint32_t)((2 * ks + bhalf) ^ l7) << 4;
            uint32_t ah[4][4], bh[2][4];
            #pragma unroll
            for (int mt = 0; mt < 4; mt++)
                ldsm4(ah[mt], sb + OFF_WHI + aoff[mt] + acol);
            #pragma unroll
            for (int np = 0; np < 2; np++)
                ldsm4(bh[np], sb + OFF_XHI + boff[np] + bcol);
            #pragma unroll
            for (int mt = 0; mt < 4; mt++)
                #pragma unroll
                for (int nt = 0; nt < 4; nt++)
                    mma_f32(acc[mt][nt], ah[mt], &bh[nt >> 1][(nt & 1) * 2]);
        }
    }

    #pragma unroll
    for (int mt = 0; mt < 4; mt++) {
        const int r0 = co0 + wm * 64 + mt * 16 + (lane >> 2);
        const size_t mb0 = ((size_t)u * IN_CH + r0) * TPAD;
        const size_t mb1 = ((size_t)u * IN_CH + r0 + 8) * TPAD;
        #pragma unroll
        for (int nt = 0; nt < 4; nt++) {
            const int p = p0 + wn * 32 + nt * 8 + ((lane & 3) << 1);
            *(float2*)&g_M[mb0 + p] = make_float2(acc[mt][nt][0], acc[mt][nt][1]);
            *(float2*)&g_M[mb1 + p] = make_float2(acc[mt][nt][2], acc[mt][nt][3]);
        }
    }
}

// ---------------- inverse transform (unchanged from passing R11) ----------------
__global__ __launch_bounds__(256)
void inv_kernel(const float* __restrict__ brpn) {
    const int idx = blockIdx.x * 256 + threadIdx.x;
    if (idx >= IN_CH * NTILES) return;
    const int co   = idx / NTILES;
    const int tile = idx - co * NTILES;
    const int b  = tile / TPB;
    const int t2 = tile - b * TPB;
    const int ty = t2 / 50;
    const int tx = t2 - ty * 50;

    float m[4][4];
    #pragma unroll
    for (int r = 0; r < 4; r++)
        #pragma unroll
        for (int s = 0; s < 4; s++)
            m[r][s] = g_M[((size_t)(r * 4 + s) * IN_CH + co) * TPAD + tile];

    float t0[4], t1[4];
    #pragma unroll
    for (int s = 0; s < 4; s++) {
        t0[s] = m[0][s] + m[1][s] + m[2][s];
        t1[s] = m[1][s] - m[2][s] - m[3][s];
    }
    const float bv = brpn[co];
    float o00 = t0[0] + t0[1] + t0[2] + bv;
    float o01 = t0[1] - t0[2] - t0[3] + bv;
    float o10 = t1[0] + t1[1] + t1[2] + bv;
    float o11 = t1[1] - t1[2] - t1[3] + bv;

    float* fb = g_feat + ((size_t)(b * IN_CH + co)) * (HH * WW) + (size_t)(2 * ty) * WW + 2 * tx;
    *(float2*)fb        = make_float2(fmaxf(o00, 0.0f), fmaxf(o01, 0.0f));
    *(float2*)(fb + WW) = make_float2(fmaxf(o10, 0.0f), fmaxf(o11, 0.0f));
}

// ---------------- heads stage A: FFMA2 co-pairs (bit-identical math) ----------------
__global__ __launch_bounds__(256)
void headsA_kernel() {
    __shared__ unsigned long long sw2[128][24];            // packed co-pairs per ci
    const int c = blockIdx.y;
    const int idx = blockIdx.x * 256 + threadIdx.x;
    const bool active = idx < NPOSOUT;
    const int b = idx / (HH * WW);
    const int hw = idx % (HH * WW);
    const float* fp = g_feat + ((size_t)b * IN_CH + c * 128) * (HH * WW) + hw;

    // g_wh rows are 48 floats = 24 u64 (8B-aligned)
    for (int e = threadIdx.x; e < 128 * 24; e += 256)
        ((unsigned long long*)sw2)[e] =
            ((const unsigned long long*)g_wh)[(size_t)(c * 128) * 24 + e];
    __syncthreads();

    if (!active) return;

    unsigned long long acc[24];
    #pragma unroll
    for (int q = 0; q < 24; q++) acc[q] = 0ull;            // packed (0.0f, 0.0f)

    for (int ci = 0; ci < 128; ci++) {
        float v = fp[(size_t)ci * (HH * WW)];
        unsigned long long vv = pk2(v, v);
        const unsigned long long* wr = sw2[ci];
        #pragma unroll
        for (int q = 0; q < 24; q++) fma2(acc[q], vv, wr[q]);
    }

    #pragma unroll
    for (int q = 0; q < 23; q++) {
        float lo, hi;
        upk2(acc[q], lo, hi);
        int co = 2 * q;
        g_part[((size_t)(c * NHEAD + co)) * NPOSOUT + idx] = lo;
        if (co + 1 < NHEAD)
            g_part[((size_t)(c * NHEAD + co + 1)) * NPOSOUT + idx] = hi;
    }
}

// ---------------- heads stage B (unchanged from passing R8-R11) ----------------
__global__ __launch_bounds__(256)
void headsB_kernel(const float* __restrict__ bcls, const float* __restrict__ bbbox,
                   float* __restrict__ out) {
    const int e = blockIdx.x * 256 + threadIdx.x;
    if (e >= NHEAD * NPOSOUT) return;
    const int co = e / NPOSOUT;
    const int pos = e % NPOSOUT;
    float s = g_part[e]
            + g_part[e + 1 * NHEAD * NPOSOUT]
            + g_part[e + 2 * NHEAD * NPOSOUT]
            + g_part[e + 3 * NHEAD * NPOSOUT];
    const int b = pos / (HH * WW);
    const int hw = pos % (HH * WW);
    if (co < NA) {
        out[((size_t)(b * NA + co)) * (HH * WW) + hw] = s + bcls[co];
    } else {
        const int j = co - NA;
        out[(size_t)BATCH * NA * (HH * WW) + ((size_t)(b * 36 + j)) * (HH * WW) + hw]
            = s + bbbox[j];
    }
}

// ---------------- launch ----------------
extern "C" void kernel_launch(void* const* d_in, const int* in_sizes, int n_in,
                              void* d_out, int out_size) {
    const float* x      = (const float*)d_in[0];
    const float* w_rpn  = (const float*)d_in[1];
    const float* b_rpn  = (const float*)d_in[2];
    const float* w_cls  = (const float*)d_in[3];
    const float* b_cls  = (const float*)d_in[4];
    const float* w_bbox = (const float*)d_in[5];
    const float* b_bbox = (const float*)d_in[6];
    float* out = (float*)d_out;

    cudaFuncSetAttribute(gemm_mma, cudaFuncAttributeMaxDynamicSharedMemorySize, DSMEM_BYTES);

    wt_kernel<<<(IN_CH * IN_CH + 255) / 256, 256>>>(w_rpn);
    transform_whead<<<(IN_CH * NHEADP + 255) / 256, 256>>>(w_cls, w_bbox);
    xborder_kernel<<<(BATCH * 404 * IN_CH + 255) / 256, 256>>>();
    xpad_kernel<<<dim3(4, HH, BATCH), dim3(32, 8)>>>(x);
    xt_kernel<<<dim3(50, 5, BATCH), 256>>>();

    gemm_mma<<<dim3(IN_CH / BM, TBLK, NU), 256, DSMEM_BYTES>>>();

    inv_kernel<<<(IN_CH * NTILES + 255) / 256, 256>>>(b_rpn);

    headsA_kernel<<<dim3((NPOSOUT + 255) / 256, 4), 256>>>();
    headsB_kernel<<<(NHEAD * NPOSOUT + 255) / 256, 256>>>(b_cls, b_bbox, out);
}